// round 10
// baseline (speedup 1.0000x reference)
#include <cuda_runtime.h>
#include <cuda_fp16.h>
#include <cstdint>

#define NN   50000
#define EE   600000
#define FEAT 11
#define DD   128
#define BBATCH 500
#define MAXA 100
#define NLAYERS 5
#define DENSE (BBATCH*MAXA*DD)   /* 6,400,000 */
#define MASKN (BBATCH*MAXA)      /* 50,000 */

#define SCAN_BS   1024
#define SCAN_NB   ((NN + SCAN_BS - 1) / SCAN_BS)   /* 49 */

#define TILE_M    128
#define GEMM_NB   ((NN + TILE_M - 1) / TILE_M)     /* 391 */
#define NNP       (GEMM_NB * TILE_M)               /* 50048, padded */

// -------- scratch (static device globals; zero-initialized, no runtime alloc) --------
__device__ __half g_y[NN*DD];                  // y = dinv * x, fp16 (12.8 MB)
__device__ __half g_apk[NNP*DD];               // aggregated A, fp16 (12.8 MB; pad rows stay 0)
__device__ __half g_wpk[NLAYERS*DD*DD*2];      // packed Wt [l][n]: {hi01, lo01, hi23, lo23}
__device__ float g_dinv[NN];
__device__ int   g_deg[NN];
__device__ int   g_rowstart[NN+1];
__device__ int   g_cursor[NN];
__device__ int   g_csr_src[EE];
__device__ int   g_counts[BBATCH];
__device__ int   g_ptr[BBATCH];
__device__ int   g_bsum[SCAN_NB];
__device__ int   g_boff[SCAN_NB];

// ---------------- graph preprocessing ----------------
__global__ void k_zero()
{
    int i = blockIdx.x * blockDim.x + threadIdx.x;
    if (i < NN) g_deg[i] = 0;
    if (i < BBATCH) g_counts[i] = 0;
}

__global__ void k_hist(const int* __restrict__ col, const int* __restrict__ batch)
{
    int i = blockIdx.x * blockDim.x + threadIdx.x;
    if (i < EE) atomicAdd(&g_deg[col[i]], 1);
    if (i < NN) atomicAdd(&g_counts[batch[i]], 1);
}

// scan1 also computes dinv (deg value already in hand)
__global__ __launch_bounds__(SCAN_BS)
void k_scan1()
{
    __shared__ int warp_sums[32];
    int tid  = threadIdx.x;
    int lane = tid & 31;
    int wid  = tid >> 5;
    int i    = blockIdx.x * SCAN_BS + tid;

    int v0 = (i < NN) ? g_deg[i] : 0;
    if (i < NN) {
        g_dinv[i] = rsqrtf((float)v0 + 2.0f);
    }
    int v  = v0;
    #pragma unroll
    for (int off = 1; off < 32; off <<= 1) {
        int t = __shfl_up_sync(0xffffffffu, v, off);
        if (lane >= off) v += t;
    }
    if (lane == 31) warp_sums[wid] = v;
    __syncthreads();
    if (wid == 0) {
        int s = warp_sums[lane];
        #pragma unroll
        for (int off = 1; off < 32; off <<= 1) {
            int t = __shfl_up_sync(0xffffffffu, s, off);
            if (lane >= off) s += t;
        }
        warp_sums[lane] = s;
    }
    __syncthreads();
    int incl = v + (wid ? warp_sums[wid-1] : 0);
    if (i < NN) {
        g_rowstart[i+1] = incl;
        g_cursor[i]     = incl - v0;
    }
    if (tid == SCAN_BS - 1) g_bsum[blockIdx.x] = incl;
}

__global__ __launch_bounds__(512)
void k_scan2()
{
    __shared__ int sb[64];
    __shared__ int warp_sums[16];
    int tid  = threadIdx.x;
    int lane = tid & 31;
    int wid  = tid >> 5;

    if (tid < 64) sb[tid] = (tid < SCAN_NB) ? g_bsum[tid] : 0;
    __syncthreads();
    #pragma unroll
    for (int off = 1; off < 64; off <<= 1) {
        int t = 0;
        if (tid < 64 && tid >= off) t = sb[tid - off];
        __syncthreads();
        if (tid < 64) sb[tid] += t;
        __syncthreads();
    }
    if (tid < SCAN_NB) g_boff[tid] = (tid == 0) ? 0 : sb[tid - 1];
    if (tid == 0) g_rowstart[0] = 0;

    int c = (tid < BBATCH) ? g_counts[tid] : 0;
    int v = c;
    #pragma unroll
    for (int off = 1; off < 32; off <<= 1) {
        int t = __shfl_up_sync(0xffffffffu, v, off);
        if (lane >= off) v += t;
    }
    if (lane == 31) warp_sums[wid] = v;
    __syncthreads();
    if (wid == 0 && lane < 16) {
        int s = warp_sums[lane];
        #pragma unroll
        for (int off = 1; off < 16; off <<= 1) {
            int t = __shfl_up_sync(0xffffu, s, off);
            if (lane >= off) s += t;
        }
        warp_sums[lane] = s;
    }
    __syncthreads();
    int incl = v + (wid ? warp_sums[wid-1] : 0);
    if (tid < BBATCH) g_ptr[tid] = incl - c;
}

__global__ __launch_bounds__(SCAN_BS)
void k_scan3()
{
    int i = blockIdx.x * SCAN_BS + threadIdx.x;
    if (i >= NN) return;
    int off = g_boff[blockIdx.x];
    g_rowstart[i+1] += off;
    g_cursor[i]     += off;
}

// csr build (indices only) + mask write
__global__ void k_csr(const int* __restrict__ conn, const int* __restrict__ batch,
                      float* __restrict__ out, int out_size)
{
    int e = blockIdx.x * blockDim.x + threadIdx.x;
    if (e < NN && out_size >= DENSE + MASKN) {
        int b = batch[e];
        out[DENSE + b*MAXA + (e - g_ptr[b])] = 1.0f;
    }
    if (e >= EE) return;
    int r = conn[e];
    int c = conn[EE + e];
    int slot = atomicAdd(&g_cursor[c], 1);
    g_csr_src[slot] = r;
}

// ---- transpose W to [l][n][k], split fp16 hi/lo, interleave per word-pair ----
__global__ void k_prepw(const float* __restrict__ Ws)
{
    int idx = blockIdx.x * blockDim.x + threadIdx.x;
    if (idx >= NLAYERS*DD*DD) return;
    int l = idx >> 14;
    int r = idx & 16383;
    int n = r >> 7;
    int k = r & 127;
    float v = Ws[l*DD*DD + k*DD + n];
    __half hi = __float2half_rn(v);
    __half lo = __float2half_rn(v - __half2float(hi));
    int base = (l*DD + n) * 256 + (k >> 1) * 4 + (k & 1);
    g_wpk[base]     = hi;
    g_wpk[base + 2] = lo;
}

// ---------------- log-expansion: y0 = dinv * (log(atoms+1) @ W_exp + b_exp) ----------------
__global__ void k_expand(const float* __restrict__ atoms,
                         const float* __restrict__ Wexp,
                         const float* __restrict__ bexp)
{
    __shared__ float sW[FEAT*DD];
    __shared__ float sb[DD];
    __shared__ float la[FEAT];
    int tid = threadIdx.x;
    for (int i = tid; i < FEAT*DD; i += DD) sW[i] = Wexp[i];
    sb[tid] = bexp[tid];
    for (int n = blockIdx.x; n < NN; n += gridDim.x) {
        __syncthreads();
        if (tid < FEAT) la[tid] = logf(atoms[n*FEAT + tid] + 1.0f);
        __syncthreads();
        float acc = sb[tid];
        #pragma unroll
        for (int f = 0; f < FEAT; f++) acc = fmaf(la[f], sW[f*DD + tid], acc);
        g_y[n*DD + tid] = __float2half(acc * g_dinv[n]);
    }
}

// ---- aggregation: 2 nodes per warp (16 lanes each, uint4 = 8 halves per lane) ----
// agg[w] = dinv[w] * (sum_src y[src] + 2*y[w]), emitted fp16
__global__ void k_agg(const __half* __restrict__ y)
{
    int gwarp = (blockIdx.x * blockDim.x + threadIdx.x) >> 5;
    int lane  = threadIdx.x & 31;
    int w     = gwarp * 2 + (lane >> 4);   // node for this half-warp
    int hl    = lane & 15;                 // 0..15 -> uint4 chunk within row
    if (w >= NN) return;

    const uint4* yr = reinterpret_cast<const uint4*>(y);   // 16 uint4 per row

    uint4 sv = yr[w*16 + hl];
    float acc[8];
    {
        const __half2* hp = reinterpret_cast<const __half2*>(&sv);
        #pragma unroll
        for (int q = 0; q < 4; q++) {
            float2 f = __half22float2(hp[q]);
            acc[q*2]   = 2.f * f.x;
            acc[q*2+1] = 2.f * f.y;
        }
    }

    int s = g_rowstart[w];
    int e = g_rowstart[w+1];
    int j = s;
    for (; j + 4 <= e; j += 4) {
        int i0 = g_csr_src[j],   i1 = g_csr_src[j+1];
        int i2 = g_csr_src[j+2], i3 = g_csr_src[j+3];
        uint4 u0 = yr[i0*16 + hl];
        uint4 u1 = yr[i1*16 + hl];
        uint4 u2 = yr[i2*16 + hl];
        uint4 u3 = yr[i3*16 + hl];
        const __half2* p0 = reinterpret_cast<const __half2*>(&u0);
        const __half2* p1 = reinterpret_cast<const __half2*>(&u1);
        const __half2* p2 = reinterpret_cast<const __half2*>(&u2);
        const __half2* p3 = reinterpret_cast<const __half2*>(&u3);
        #pragma unroll
        for (int q = 0; q < 4; q++) {
            float2 f0 = __half22float2(p0[q]);
            float2 f1 = __half22float2(p1[q]);
            float2 f2 = __half22float2(p2[q]);
            float2 f3 = __half22float2(p3[q]);
            acc[q*2]   += f0.x + f1.x + f2.x + f3.x;
            acc[q*2+1] += f0.y + f1.y + f2.y + f3.y;
        }
    }
    for (; j < e; j++) {
        int src = g_csr_src[j];
        uint4 u = yr[src*16 + hl];
        const __half2* p = reinterpret_cast<const __half2*>(&u);
        #pragma unroll
        for (int q = 0; q < 4; q++) {
            float2 f = __half22float2(p[q]);
            acc[q*2]   += f.x;
            acc[q*2+1] += f.y;
        }
    }

    float di = g_dinv[w];
    uint4 pkt;
    __half2 h0 = __floats2half2_rn(acc[0]*di, acc[1]*di);
    __half2 h1 = __floats2half2_rn(acc[2]*di, acc[3]*di);
    __half2 h2 = __floats2half2_rn(acc[4]*di, acc[5]*di);
    __half2 h3 = __floats2half2_rn(acc[6]*di, acc[7]*di);
    pkt.x = *reinterpret_cast<uint32_t*>(&h0);
    pkt.y = *reinterpret_cast<uint32_t*>(&h1);
    pkt.z = *reinterpret_cast<uint32_t*>(&h2);
    pkt.w = *reinterpret_cast<uint32_t*>(&h3);
    reinterpret_cast<uint4*>(g_apk)[w*16 + hl] = pkt;
}

// ---------------- fp16 mma.sync GEMM: relu(A(Whi+Wlo)^T + b) ----------------
__device__ __forceinline__ void mma_f16(float* d, const uint32_t* a, const uint32_t* b)
{
    asm volatile(
        "mma.sync.aligned.m16n8k16.row.col.f32.f16.f16.f32 "
        "{%0,%1,%2,%3}, {%4,%5,%6,%7}, {%8,%9}, {%0,%1,%2,%3};"
        : "+f"(d[0]), "+f"(d[1]), "+f"(d[2]), "+f"(d[3])
        : "r"(a[0]), "r"(a[1]), "r"(a[2]), "r"(a[3]), "r"(b[0]), "r"(b[1]));
}

// non-LAST: writes y = dinv*relu(..) as fp16. LAST: scatters fp32 into dense out.
template<bool LAST>
__global__ __launch_bounds__(256)
void k_gemm_mma(const __half* __restrict__ apk,
                const __half* __restrict__ wpk,
                const float* __restrict__ bias,
                __half* __restrict__ yout,
                float* __restrict__ dout,
                const int* __restrict__ batch)
{
    int tid    = threadIdx.x;
    int lane   = tid & 31;
    int wid    = tid >> 5;
    int warp_m = wid & 3;
    int warp_n = wid >> 2;
    int g      = lane >> 2;
    int tq     = lane & 3;

    int rowBase = blockIdx.x * TILE_M + warp_m * 32;
    int colBase = warp_n * 64;

    const uint32_t* AP = reinterpret_cast<const uint32_t*>(apk);   // 64 words per row
    const uint2*    BP = reinterpret_cast<const uint2*>(wpk);      // 64 {hi,lo} pairs per row

    const uint32_t* a0 = AP + (rowBase + g     ) * 64;
    const uint32_t* a1 = AP + (rowBase + g +  8) * 64;
    const uint32_t* a2 = AP + (rowBase + g + 16) * 64;
    const uint32_t* a3 = AP + (rowBase + g + 24) * 64;
    const uint2*    bp = BP + (colBase + g) * 64;

    float d[2][8][4];
    #pragma unroll
    for (int mt = 0; mt < 2; mt++)
        #pragma unroll
        for (int nt = 0; nt < 8; nt++)
            #pragma unroll
            for (int q = 0; q < 4; q++) d[mt][nt][q] = 0.0f;

    #pragma unroll 4
    for (int ks = 0; ks < 8; ks++) {
        int o0 = ks*8 + tq;
        int o1 = o0 + 4;

        uint32_t aF[2][4];
        aF[0][0] = a0[o0]; aF[0][1] = a1[o0]; aF[0][2] = a0[o1]; aF[0][3] = a1[o1];
        aF[1][0] = a2[o0]; aF[1][1] = a3[o0]; aF[1][2] = a2[o1]; aF[1][3] = a3[o1];

        uint32_t bHf[8][2], bLf[8][2];
        #pragma unroll
        for (int nt = 0; nt < 8; nt++) {
            uint2 w0 = bp[nt*512 + o0];
            uint2 w1 = bp[nt*512 + o1];
            bHf[nt][0] = w0.x; bHf[nt][1] = w1.x;
            bLf[nt][0] = w0.y; bLf[nt][1] = w1.y;
        }
        #pragma unroll
        for (int mt = 0; mt < 2; mt++)
            #pragma unroll
            for (int nt = 0; nt < 8; nt++)
                mma_f16(d[mt][nt], aF[mt], bHf[nt]);
        #pragma unroll
        for (int mt = 0; mt < 2; mt++)
            #pragma unroll
            for (int nt = 0; nt < 8; nt++)
                mma_f16(d[mt][nt], aF[mt], bLf[nt]);
    }

    #pragma unroll
    for (int mt = 0; mt < 2; mt++) {
        int m0 = rowBase + mt*16 + g;
        int m1 = m0 + 8;
        if (LAST) {
            int or0 = 0, or1 = 0;
            if (m0 < NN) { int b = batch[m0]; or0 = b*MAXA + (m0 - g_ptr[b]); }
            if (m1 < NN) { int b = batch[m1]; or1 = b*MAXA + (m1 - g_ptr[b]); }
            #pragma unroll
            for (int nt = 0; nt < 8; nt++) {
                int cn = colBase + nt*8 + tq*2;
                float2 bv = *reinterpret_cast<const float2*>(bias + cn);
                if (m0 < NN) {
                    float2 o;
                    o.x = fmaxf(d[mt][nt][0] + bv.x, 0.f);
                    o.y = fmaxf(d[mt][nt][1] + bv.y, 0.f);
                    *reinterpret_cast<float2*>(dout + or0*DD + cn) = o;
                }
                if (m1 < NN) {
                    float2 o;
                    o.x = fmaxf(d[mt][nt][2] + bv.x, 0.f);
                    o.y = fmaxf(d[mt][nt][3] + bv.y, 0.f);
                    *reinterpret_cast<float2*>(dout + or1*DD + cn) = o;
                }
            }
        } else {
            float di0 = (m0 < NN) ? g_dinv[m0] : 0.f;
            float di1 = (m1 < NN) ? g_dinv[m1] : 0.f;
            #pragma unroll
            for (int nt = 0; nt < 8; nt++) {
                int cn = colBase + nt*8 + tq*2;
                float2 bv = *reinterpret_cast<const float2*>(bias + cn);
                if (m0 < NN) {
                    float ox = fmaxf(d[mt][nt][0] + bv.x, 0.f) * di0;
                    float oy = fmaxf(d[mt][nt][1] + bv.y, 0.f) * di0;
                    *reinterpret_cast<__half2*>(yout + m0*DD + cn) = __floats2half2_rn(ox, oy);
                }
                if (m1 < NN) {
                    float ox = fmaxf(d[mt][nt][2] + bv.x, 0.f) * di1;
                    float oy = fmaxf(d[mt][nt][3] + bv.y, 0.f) * di1;
                    *reinterpret_cast<__half2*>(yout + m1*DD + cn) = __floats2half2_rn(ox, oy);
                }
            }
        }
    }
}

// ---------------- tail zero (only for any region beyond dense+mask) ----------------
__global__ void k_zero_tail(float* __restrict__ out, int start, int n)
{
    int i = blockIdx.x * blockDim.x + threadIdx.x;
    if (i < n) out[start + i] = 0.0f;
}

// ---------------- launch ----------------
extern "C" void kernel_launch(void* const* d_in, const int* in_sizes, int n_in,
                              void* d_out, int out_size)
{
    const float* atoms = (const float*)d_in[0];
    const int*   conn  = (const int*)d_in[1];
    const int*   batch = (const int*)d_in[2];
    const float* W_exp = (const float*)d_in[3];
    const float* b_exp = (const float*)d_in[4];
    const float* Ws    = (const float*)d_in[5];
    const float* bs    = (const float*)d_in[6];
    float* out = (float*)d_out;

    __half *py, *papk, *pwpk;
    cudaGetSymbolAddress((void**)&py,   g_y);
    cudaGetSymbolAddress((void**)&papk, g_apk);
    cudaGetSymbolAddress((void**)&pwpk, g_wpk);

    k_zero<<<(NN + 255)/256, 256>>>();
    k_hist<<<(EE + 255)/256, 256>>>(conn + EE, batch);
    k_scan1<<<SCAN_NB, SCAN_BS>>>();
    k_scan2<<<1, 512>>>();
    k_scan3<<<SCAN_NB, SCAN_BS>>>();
    k_csr<<<(EE + 255)/256, 256>>>(conn, batch, out, out_size);
    k_prepw<<<(NLAYERS*DD*DD + 255)/256, 256>>>(Ws);
    k_expand<<<4096, DD>>>(atoms, W_exp, b_exp);

    int tail = out_size - (DENSE + MASKN);
    if (tail > 0)
        k_zero_tail<<<(tail + 255)/256, 256>>>(out, DENSE + MASKN, tail);

    // 2 nodes per warp -> 25000 warps -> blocks of 8 warps
    int aggBlocks = ((NN + 1)/2 + 7) / 8;
    for (int l = 0; l < NLAYERS - 1; l++) {
        k_agg<<<aggBlocks, 256>>>(py);
        k_gemm_mma<false><<<GEMM_NB, 256>>>(papk, pwpk + l*DD*DD*2, bs + l*DD, py, nullptr, batch);
    }
    k_agg<<<aggBlocks, 256>>>(py);
    k_gemm_mma<true><<<GEMM_NB, 256>>>(papk, pwpk + 4*DD*DD*2, bs + 4*DD, nullptr, out, batch);
}

// round 11
// speedup vs baseline: 1.0402x; 1.0402x over previous
#include <cuda_runtime.h>
#include <cuda_fp16.h>
#include <cstdint>

#define NN   50000
#define EE   600000
#define FEAT 11
#define DD   128
#define BBATCH 500
#define MAXA 100
#define NLAYERS 5
#define DENSE (BBATCH*MAXA*DD)   /* 6,400,000 */
#define MASKN (BBATCH*MAXA)      /* 50,000 */

#define SCAN_BS   1024
#define SCAN_NB   ((NN + SCAN_BS - 1) / SCAN_BS)   /* 49 */

#define TILE_M    128
#define GEMM_NB   ((NN + TILE_M - 1) / TILE_M)     /* 391 */
#define NNP       (GEMM_NB * TILE_M)               /* 50048, padded */

// merged-kernel block ranges
#define ZB   ((NN + 255)/256)                      /* 196  zero blocks   */
#define PWB  ((NLAYERS*DD*DD + 255)/256)           /* 320  prepw blocks  */
#define CSRB ((EE + 255)/256)                      /* 2344 csr blocks    */
#define EXPB ((NN + 7)/8)                          /* 6250 expand blocks */

// -------- scratch (static device globals; zero-initialized, no runtime alloc) --------
__device__ __half g_y[NN*DD];                  // y = dinv * x, fp16 (12.8 MB)
__device__ __half g_apk[NNP*DD];               // aggregated A, fp16 (12.8 MB; pad rows stay 0)
__device__ __half g_wpk[NLAYERS*DD*DD*2];      // packed Wt [l][n]: {hi01, lo01, hi23, lo23}
__device__ float g_dinv[NN];
__device__ int   g_deg[NN];
__device__ int   g_rowstart[NN+1];
__device__ int   g_cursor[NN];
__device__ int   g_csr_src[EE];
__device__ int   g_counts[BBATCH];
__device__ int   g_ptr[BBATCH];
__device__ int   g_bsum[SCAN_NB];

// ---------------- prep: zero + W transpose/split (independent, merged) ----------------
__global__ void k_zero_prepw(const float* __restrict__ Ws)
{
    if (blockIdx.x < ZB) {
        int i = blockIdx.x * 256 + threadIdx.x;
        if (i < NN) g_deg[i] = 0;
        if (i < BBATCH) g_counts[i] = 0;
        return;
    }
    int idx = (blockIdx.x - ZB) * 256 + threadIdx.x;
    if (idx >= NLAYERS*DD*DD) return;
    int l = idx >> 14;
    int r = idx & 16383;
    int n = r >> 7;
    int k = r & 127;
    float v = Ws[l*DD*DD + k*DD + n];
    __half hi = __float2half_rn(v);
    __half lo = __float2half_rn(v - __half2float(hi));
    int base = (l*DD + n) * 256 + (k >> 1) * 4 + (k & 1);
    g_wpk[base]     = hi;
    g_wpk[base + 2] = lo;
}

__global__ void k_hist(const int* __restrict__ col, const int* __restrict__ batch)
{
    int i = blockIdx.x * blockDim.x + threadIdx.x;
    if (i < EE) atomicAdd(&g_deg[col[i]], 1);
    if (i < NN) atomicAdd(&g_counts[batch[i]], 1);
}

// scan1: block-local inclusive scan of deg + dinv + per-block sums
__global__ __launch_bounds__(SCAN_BS)
void k_scan1()
{
    __shared__ int warp_sums[32];
    int tid  = threadIdx.x;
    int lane = tid & 31;
    int wid  = tid >> 5;
    int i    = blockIdx.x * SCAN_BS + tid;

    int v0 = (i < NN) ? g_deg[i] : 0;
    if (i < NN) {
        g_dinv[i] = rsqrtf((float)v0 + 2.0f);
    }
    int v  = v0;
    #pragma unroll
    for (int off = 1; off < 32; off <<= 1) {
        int t = __shfl_up_sync(0xffffffffu, v, off);
        if (lane >= off) v += t;
    }
    if (lane == 31) warp_sums[wid] = v;
    __syncthreads();
    if (wid == 0) {
        int s = warp_sums[lane];
        #pragma unroll
        for (int off = 1; off < 32; off <<= 1) {
            int t = __shfl_up_sync(0xffffffffu, s, off);
            if (lane >= off) s += t;
        }
        warp_sums[lane] = s;
    }
    __syncthreads();
    int incl = v + (wid ? warp_sums[wid-1] : 0);
    if (i < NN) {
        g_rowstart[i+1] = incl;
        g_cursor[i]     = incl - v0;
    }
    if (tid == SCAN_BS - 1) g_bsum[blockIdx.x] = incl;
}

// scan3': every block redundantly computes the 49-block prefix; block 0 also counts->ptr
__global__ __launch_bounds__(SCAN_BS)
void k_scan3()
{
    __shared__ int sb[64];
    __shared__ int warp_sums[32];
    int tid = threadIdx.x;

    if (tid < 64) sb[tid] = (tid < SCAN_NB) ? g_bsum[tid] : 0;
    __syncthreads();
    #pragma unroll
    for (int off = 1; off < 64; off <<= 1) {
        int t = 0;
        if (tid < 64 && tid >= off) t = sb[tid - off];
        __syncthreads();
        if (tid < 64) sb[tid] += t;
        __syncthreads();
    }
    int boff = (blockIdx.x == 0) ? 0 : sb[blockIdx.x - 1];

    int i = blockIdx.x * SCAN_BS + tid;
    if (i < NN) {
        g_rowstart[i+1] += boff;
        g_cursor[i]     += boff;
    }

    if (blockIdx.x == 0) {
        if (tid == 0) g_rowstart[0] = 0;
        // exclusive scan of counts[500] -> ptr (all 1024 threads participate)
        int lane = tid & 31;
        int wid  = tid >> 5;
        int c = (tid < BBATCH) ? g_counts[tid] : 0;
        int v = c;
        #pragma unroll
        for (int off = 1; off < 32; off <<= 1) {
            int t = __shfl_up_sync(0xffffffffu, v, off);
            if (lane >= off) v += t;
        }
        if (lane == 31) warp_sums[wid] = v;
        __syncthreads();
        if (wid == 0) {
            int s = warp_sums[lane];
            #pragma unroll
            for (int off = 1; off < 32; off <<= 1) {
                int t = __shfl_up_sync(0xffffffffu, s, off);
                if (lane >= off) s += t;
            }
            warp_sums[lane] = s;
        }
        __syncthreads();
        int incl = v + (wid ? warp_sums[wid-1] : 0);
        if (tid < BBATCH) g_ptr[tid] = incl - c;
    }
}

// ---- merged: csr build + mask write + log-expansion (all ready after scan3) ----
// blocks [0, CSRB): csr (thread e) + mask (e < NN)
// blocks [CSRB, CSRB+EXPB): expand, warp-per-node (8 nodes per block)
__global__ __launch_bounds__(256)
void k_csr_expand(const int* __restrict__ conn, const int* __restrict__ batch,
                  float* __restrict__ out, int out_size,
                  const float* __restrict__ atoms,
                  const float* __restrict__ Wexp,
                  const float* __restrict__ bexp)
{
    __shared__ float sW[FEAT*DD];
    __shared__ float sb[DD];

    if (blockIdx.x < CSRB) {
        int e = blockIdx.x * 256 + threadIdx.x;
        if (e < NN && out_size >= DENSE + MASKN) {
            int b = batch[e];
            out[DENSE + b*MAXA + (e - g_ptr[b])] = 1.0f;
        }
        if (e >= EE) return;
        int r = conn[e];
        int c = conn[EE + e];
        int slot = atomicAdd(&g_cursor[c], 1);
        g_csr_src[slot] = r;
        return;
    }

    // ---- expansion: y0 = dinv * (log(atoms+1) @ W_exp + b_exp) ----
    int tid = threadIdx.x;
    for (int i = tid; i < FEAT*DD; i += 256) sW[i] = Wexp[i];
    if (tid < DD) sb[tid] = bexp[tid];
    __syncthreads();

    int nb   = blockIdx.x - CSRB;
    int wid  = tid >> 5;
    int lane = tid & 31;
    int n    = nb * 8 + wid;
    if (n >= NN) return;

    float la = 0.f;
    if (lane < FEAT) la = logf(atoms[n*FEAT + lane] + 1.0f);

    int d0 = lane * 4;               // 4 contiguous dims per lane
    float acc[4];
    #pragma unroll
    for (int q = 0; q < 4; q++) acc[q] = sb[d0 + q];
    #pragma unroll
    for (int f = 0; f < FEAT; f++) {
        float lf = __shfl_sync(0xffffffffu, la, f);
        #pragma unroll
        for (int q = 0; q < 4; q++)
            acc[q] = fmaf(lf, sW[f*DD + d0 + q], acc[q]);
    }
    float di = g_dinv[n];
    __half2 h0 = __floats2half2_rn(acc[0]*di, acc[1]*di);
    __half2 h1 = __floats2half2_rn(acc[2]*di, acc[3]*di);
    uint2 p;
    p.x = *reinterpret_cast<uint32_t*>(&h0);
    p.y = *reinterpret_cast<uint32_t*>(&h1);
    reinterpret_cast<uint2*>(g_y)[n*32 + lane] = p;
}

// ------- aggregation: agg[w] = dinv[w]*(sum_src y[src] + 2*y[w]), emitted fp16 -------
__global__ void k_agg(const __half* __restrict__ y)
{
    int w = (blockIdx.x * blockDim.x + threadIdx.x) >> 5;
    if (w >= NN) return;
    int lane = threadIdx.x & 31;
    const uint2* yr = reinterpret_cast<const uint2*>(y);   // 32 uint2 per row

    uint2 sv = yr[w*32 + lane];
    float2 s0 = __half22float2(*reinterpret_cast<__half2*>(&sv.x));
    float2 s1 = __half22float2(*reinterpret_cast<__half2*>(&sv.y));
    float4 acc = make_float4(2.f*s0.x, 2.f*s0.y, 2.f*s1.x, 2.f*s1.y);

    int s = g_rowstart[w];
    int e = g_rowstart[w+1];
    int j = s;
    for (; j + 4 <= e; j += 4) {
        int   i0 = g_csr_src[j],   i1 = g_csr_src[j+1];
        int   i2 = g_csr_src[j+2], i3 = g_csr_src[j+3];
        uint2 u0 = yr[i0*32 + lane];
        uint2 u1 = yr[i1*32 + lane];
        uint2 u2 = yr[i2*32 + lane];
        uint2 u3 = yr[i3*32 + lane];
        float2 a0 = __half22float2(*reinterpret_cast<__half2*>(&u0.x));
        float2 b0 = __half22float2(*reinterpret_cast<__half2*>(&u0.y));
        float2 a1 = __half22float2(*reinterpret_cast<__half2*>(&u1.x));
        float2 b1 = __half22float2(*reinterpret_cast<__half2*>(&u1.y));
        float2 a2 = __half22float2(*reinterpret_cast<__half2*>(&u2.x));
        float2 b2 = __half22float2(*reinterpret_cast<__half2*>(&u2.y));
        float2 a3 = __half22float2(*reinterpret_cast<__half2*>(&u3.x));
        float2 b3 = __half22float2(*reinterpret_cast<__half2*>(&u3.y));
        acc.x += a0.x + a1.x + a2.x + a3.x;
        acc.y += a0.y + a1.y + a2.y + a3.y;
        acc.z += b0.x + b1.x + b2.x + b3.x;
        acc.w += b0.y + b1.y + b2.y + b3.y;
    }
    for (; j < e; j++) {
        int   src = g_csr_src[j];
        uint2 u   = yr[src*32 + lane];
        float2 a  = __half22float2(*reinterpret_cast<__half2*>(&u.x));
        float2 b  = __half22float2(*reinterpret_cast<__half2*>(&u.y));
        acc.x += a.x; acc.y += a.y; acc.z += b.x; acc.w += b.y;
    }

    float di = g_dinv[w];
    __half2 h0 = __floats2half2_rn(acc.x*di, acc.y*di);
    __half2 h1 = __floats2half2_rn(acc.z*di, acc.w*di);
    uint2 p;
    p.x = *reinterpret_cast<uint32_t*>(&h0);
    p.y = *reinterpret_cast<uint32_t*>(&h1);
    reinterpret_cast<uint2*>(g_apk)[w*32 + lane] = p;
}

// ---------------- fp16 mma.sync GEMM: relu(A(Whi+Wlo)^T + b) ----------------
__device__ __forceinline__ void mma_f16(float* d, const uint32_t* a, const uint32_t* b)
{
    asm volatile(
        "mma.sync.aligned.m16n8k16.row.col.f32.f16.f16.f32 "
        "{%0,%1,%2,%3}, {%4,%5,%6,%7}, {%8,%9}, {%0,%1,%2,%3};"
        : "+f"(d[0]), "+f"(d[1]), "+f"(d[2]), "+f"(d[3])
        : "r"(a[0]), "r"(a[1]), "r"(a[2]), "r"(a[3]), "r"(b[0]), "r"(b[1]));
}

// non-LAST: writes y = dinv*relu(..) as fp16. LAST: scatters fp32 into dense out.
template<bool LAST>
__global__ __launch_bounds__(256)
void k_gemm_mma(const __half* __restrict__ apk,
                const __half* __restrict__ wpk,
                const float* __restrict__ bias,
                __half* __restrict__ yout,
                float* __restrict__ dout,
                const int* __restrict__ batch)
{
    int tid    = threadIdx.x;
    int lane   = tid & 31;
    int wid    = tid >> 5;
    int warp_m = wid & 3;
    int warp_n = wid >> 2;
    int g      = lane >> 2;
    int tq     = lane & 3;

    int rowBase = blockIdx.x * TILE_M + warp_m * 32;
    int colBase = warp_n * 64;

    const uint32_t* AP = reinterpret_cast<const uint32_t*>(apk);   // 64 words per row
    const uint2*    BP = reinterpret_cast<const uint2*>(wpk);      // 64 {hi,lo} pairs per row

    const uint32_t* a0 = AP + (rowBase + g     ) * 64;
    const uint32_t* a1 = AP + (rowBase + g +  8) * 64;
    const uint32_t* a2 = AP + (rowBase + g + 16) * 64;
    const uint32_t* a3 = AP + (rowBase + g + 24) * 64;
    const uint2*    bp = BP + (colBase + g) * 64;

    float d[2][8][4];
    #pragma unroll
    for (int mt = 0; mt < 2; mt++)
        #pragma unroll
        for (int nt = 0; nt < 8; nt++)
            #pragma unroll
            for (int q = 0; q < 4; q++) d[mt][nt][q] = 0.0f;

    #pragma unroll 4
    for (int ks = 0; ks < 8; ks++) {
        int o0 = ks*8 + tq;
        int o1 = o0 + 4;

        uint32_t aF[2][4];
        aF[0][0] = a0[o0]; aF[0][1] = a1[o0]; aF[0][2] = a0[o1]; aF[0][3] = a1[o1];
        aF[1][0] = a2[o0]; aF[1][1] = a3[o0]; aF[1][2] = a2[o1]; aF[1][3] = a3[o1];

        uint32_t bHf[8][2], bLf[8][2];
        #pragma unroll
        for (int nt = 0; nt < 8; nt++) {
            uint2 w0 = bp[nt*512 + o0];
            uint2 w1 = bp[nt*512 + o1];
            bHf[nt][0] = w0.x; bHf[nt][1] = w1.x;
            bLf[nt][0] = w0.y; bLf[nt][1] = w1.y;
        }
        #pragma unroll
        for (int mt = 0; mt < 2; mt++)
            #pragma unroll
            for (int nt = 0; nt < 8; nt++)
                mma_f16(d[mt][nt], aF[mt], bHf[nt]);
        #pragma unroll
        for (int mt = 0; mt < 2; mt++)
            #pragma unroll
            for (int nt = 0; nt < 8; nt++)
                mma_f16(d[mt][nt], aF[mt], bLf[nt]);
    }

    #pragma unroll
    for (int mt = 0; mt < 2; mt++) {
        int m0 = rowBase + mt*16 + g;
        int m1 = m0 + 8;
        if (LAST) {
            int or0 = 0, or1 = 0;
            if (m0 < NN) { int b = batch[m0]; or0 = b*MAXA + (m0 - g_ptr[b]); }
            if (m1 < NN) { int b = batch[m1]; or1 = b*MAXA + (m1 - g_ptr[b]); }
            #pragma unroll
            for (int nt = 0; nt < 8; nt++) {
                int cn = colBase + nt*8 + tq*2;
                float2 bv = *reinterpret_cast<const float2*>(bias + cn);
                if (m0 < NN) {
                    float2 o;
                    o.x = fmaxf(d[mt][nt][0] + bv.x, 0.f);
                    o.y = fmaxf(d[mt][nt][1] + bv.y, 0.f);
                    *reinterpret_cast<float2*>(dout + or0*DD + cn) = o;
                }
                if (m1 < NN) {
                    float2 o;
                    o.x = fmaxf(d[mt][nt][2] + bv.x, 0.f);
                    o.y = fmaxf(d[mt][nt][3] + bv.y, 0.f);
                    *reinterpret_cast<float2*>(dout + or1*DD + cn) = o;
                }
            }
        } else {
            float di0 = (m0 < NN) ? g_dinv[m0] : 0.f;
            float di1 = (m1 < NN) ? g_dinv[m1] : 0.f;
            #pragma unroll
            for (int nt = 0; nt < 8; nt++) {
                int cn = colBase + nt*8 + tq*2;
                float2 bv = *reinterpret_cast<const float2*>(bias + cn);
                if (m0 < NN) {
                    float ox = fmaxf(d[mt][nt][0] + bv.x, 0.f) * di0;
                    float oy = fmaxf(d[mt][nt][1] + bv.y, 0.f) * di0;
                    *reinterpret_cast<__half2*>(yout + m0*DD + cn) = __floats2half2_rn(ox, oy);
                }
                if (m1 < NN) {
                    float ox = fmaxf(d[mt][nt][2] + bv.x, 0.f) * di1;
                    float oy = fmaxf(d[mt][nt][3] + bv.y, 0.f) * di1;
                    *reinterpret_cast<__half2*>(yout + m1*DD + cn) = __floats2half2_rn(ox, oy);
                }
            }
        }
    }
}

// ---------------- tail zero (only for any region beyond dense+mask) ----------------
__global__ void k_zero_tail(float* __restrict__ out, int start, int n)
{
    int i = blockIdx.x * blockDim.x + threadIdx.x;
    if (i < n) out[start + i] = 0.0f;
}

// ---------------- launch ----------------
extern "C" void kernel_launch(void* const* d_in, const int* in_sizes, int n_in,
                              void* d_out, int out_size)
{
    const float* atoms = (const float*)d_in[0];
    const int*   conn  = (const int*)d_in[1];
    const int*   batch = (const int*)d_in[2];
    const float* W_exp = (const float*)d_in[3];
    const float* b_exp = (const float*)d_in[4];
    const float* Ws    = (const float*)d_in[5];
    const float* bs    = (const float*)d_in[6];
    float* out = (float*)d_out;

    __half *py, *papk, *pwpk;
    cudaGetSymbolAddress((void**)&py,   g_y);
    cudaGetSymbolAddress((void**)&papk, g_apk);
    cudaGetSymbolAddress((void**)&pwpk, g_wpk);

    k_zero_prepw<<<ZB + PWB, 256>>>(Ws);
    k_hist<<<(EE + 255)/256, 256>>>(conn + EE, batch);
    k_scan1<<<SCAN_NB, SCAN_BS>>>();
    k_scan3<<<SCAN_NB, SCAN_BS>>>();
    k_csr_expand<<<CSRB + EXPB, 256>>>(conn, batch, out, out_size, atoms, W_exp, b_exp);

    int tail = out_size - (DENSE + MASKN);
    if (tail > 0)
        k_zero_tail<<<(tail + 255)/256, 256>>>(out, DENSE + MASKN, tail);

    int aggBlocks = (NN*32 + 255)/256;
    for (int l = 0; l < NLAYERS - 1; l++) {
        k_agg<<<aggBlocks, 256>>>(py);
        k_gemm_mma<false><<<GEMM_NB, 256>>>(papk, pwpk + l*DD*DD*2, bs + l*DD, py, nullptr, batch);
    }
    k_agg<<<aggBlocks, 256>>>(py);
    k_gemm_mma<true><<<GEMM_NB, 256>>>(papk, pwpk + 4*DD*DD*2, bs + 4*DD, nullptr, out, batch);
}

// round 12
// speedup vs baseline: 1.1301x; 1.0864x over previous
#include <cuda_runtime.h>
#include <cuda_fp16.h>
#include <cstdint>

#define NN   50000
#define EE   600000
#define FEAT 11
#define DD   128
#define BBATCH 500
#define MAXA 100
#define NLAYERS 5
#define DENSE (BBATCH*MAXA*DD)   /* 6,400,000 */
#define MASKN (BBATCH*MAXA)      /* 50,000 */

#define SCAN_BS   1024
#define SCAN_NB   ((NN + SCAN_BS - 1) / SCAN_BS)   /* 49 */

#define TILE_M    128
#define GEMM_NB   ((NN + TILE_M - 1) / TILE_M)     /* 391 */
#define NNP       (GEMM_NB * TILE_M)               /* 50048, padded */

// merged-kernel block ranges
#define ZB   ((NN + 255)/256)                      /* 196  zero blocks   */
#define PWB  ((NLAYERS*DD*DD + 255)/256)           /* 320  prepw blocks  */
#define CSRB ((EE + 255)/256)                      /* 2344 csr blocks    */
#define EXPB ((NN + 7)/8)                          /* 6250 expand blocks */

// -------- scratch (static device globals; zero-initialized, no runtime alloc) --------
__device__ __half g_y[NN*DD];                  // y = dinv * x, fp16 (12.8 MB)
__device__ __half g_apk[NNP*DD];               // aggregated A, fp16 (12.8 MB; pad rows stay 0)
__device__ __half g_wpk[NLAYERS*DD*DD];        // Wt [l][n][k] fp16, fragment-paired word order
__device__ float g_dinv[NN];
__device__ int   g_deg[NN];
__device__ int   g_rowstart[NN+1];
__device__ int   g_cursor[NN];
__device__ int   g_csr_src[EE];
__device__ int   g_counts[BBATCH];
__device__ int   g_ptr[BBATCH];
__device__ int   g_bsum[SCAN_NB];

// ---------------- prep: zero + W transpose (independent, merged) ----------------
// W row layout (per n, 128 fp16 = 64 words): word w (=k>>1) stored as
// uint2-pair index p = (w>>3)*4 + (w&3), component c = (w>>2)&1.
// So a single 8B load at pair index ks*4+tq yields the mma b-fragment {k16.lo, k16.hi}.
__global__ void k_zero_prepw(const float* __restrict__ Ws)
{
    if (blockIdx.x < ZB) {
        int i = blockIdx.x * 256 + threadIdx.x;
        if (i < NN) g_deg[i] = 0;
        if (i < BBATCH) g_counts[i] = 0;
        return;
    }
    int idx = (blockIdx.x - ZB) * 256 + threadIdx.x;
    if (idx >= NLAYERS*DD*DD) return;
    int l = idx >> 14;
    int r = idx & 16383;
    int n = r >> 7;
    int k = r & 127;
    float v = Ws[l*DD*DD + k*DD + n];
    int w = k >> 1;
    int p = ((w >> 3) << 2) | (w & 3);
    int c = (w >> 2) & 1;
    int dst = (l*DD + n) * DD + p*4 + c*2 + (k & 1);
    g_wpk[dst] = __float2half_rn(v);
}

__global__ void k_hist(const int* __restrict__ col, const int* __restrict__ batch)
{
    int i = blockIdx.x * blockDim.x + threadIdx.x;
    if (i < EE) atomicAdd(&g_deg[col[i]], 1);
    if (i < NN) atomicAdd(&g_counts[batch[i]], 1);
}

// scan1: block-local inclusive scan of deg + dinv + per-block sums
__global__ __launch_bounds__(SCAN_BS)
void k_scan1()
{
    __shared__ int warp_sums[32];
    int tid  = threadIdx.x;
    int lane = tid & 31;
    int wid  = tid >> 5;
    int i    = blockIdx.x * SCAN_BS + tid;

    int v0 = (i < NN) ? g_deg[i] : 0;
    if (i < NN) {
        g_dinv[i] = rsqrtf((float)v0 + 2.0f);
    }
    int v  = v0;
    #pragma unroll
    for (int off = 1; off < 32; off <<= 1) {
        int t = __shfl_up_sync(0xffffffffu, v, off);
        if (lane >= off) v += t;
    }
    if (lane == 31) warp_sums[wid] = v;
    __syncthreads();
    if (wid == 0) {
        int s = warp_sums[lane];
        #pragma unroll
        for (int off = 1; off < 32; off <<= 1) {
            int t = __shfl_up_sync(0xffffffffu, s, off);
            if (lane >= off) s += t;
        }
        warp_sums[lane] = s;
    }
    __syncthreads();
    int incl = v + (wid ? warp_sums[wid-1] : 0);
    if (i < NN) {
        g_rowstart[i+1] = incl;
        g_cursor[i]     = incl - v0;
    }
    if (tid == SCAN_BS - 1) g_bsum[blockIdx.x] = incl;
}

// scan3': every block redundantly computes the 49-block prefix; block 0 also counts->ptr
__global__ __launch_bounds__(SCAN_BS)
void k_scan3()
{
    __shared__ int sb[64];
    __shared__ int warp_sums[32];
    int tid = threadIdx.x;

    if (tid < 64) sb[tid] = (tid < SCAN_NB) ? g_bsum[tid] : 0;
    __syncthreads();
    #pragma unroll
    for (int off = 1; off < 64; off <<= 1) {
        int t = 0;
        if (tid < 64 && tid >= off) t = sb[tid - off];
        __syncthreads();
        if (tid < 64) sb[tid] += t;
        __syncthreads();
    }
    int boff = (blockIdx.x == 0) ? 0 : sb[blockIdx.x - 1];

    int i = blockIdx.x * SCAN_BS + tid;
    if (i < NN) {
        g_rowstart[i+1] += boff;
        g_cursor[i]     += boff;
    }

    if (blockIdx.x == 0) {
        if (tid == 0) g_rowstart[0] = 0;
        int lane = tid & 31;
        int wid  = tid >> 5;
        int c = (tid < BBATCH) ? g_counts[tid] : 0;
        int v = c;
        #pragma unroll
        for (int off = 1; off < 32; off <<= 1) {
            int t = __shfl_up_sync(0xffffffffu, v, off);
            if (lane >= off) v += t;
        }
        if (lane == 31) warp_sums[wid] = v;
        __syncthreads();
        if (wid == 0) {
            int s = warp_sums[lane];
            #pragma unroll
            for (int off = 1; off < 32; off <<= 1) {
                int t = __shfl_up_sync(0xffffffffu, s, off);
                if (lane >= off) s += t;
            }
            warp_sums[lane] = s;
        }
        __syncthreads();
        int incl = v + (wid ? warp_sums[wid-1] : 0);
        if (tid < BBATCH) g_ptr[tid] = incl - c;
    }
}

// ---- merged: csr build + mask write + log-expansion ----
__global__ __launch_bounds__(256)
void k_csr_expand(const int* __restrict__ conn, const int* __restrict__ batch,
                  float* __restrict__ out, int out_size,
                  const float* __restrict__ atoms,
                  const float* __restrict__ Wexp,
                  const float* __restrict__ bexp)
{
    __shared__ float sW[FEAT*DD];
    __shared__ float sb[DD];

    if (blockIdx.x < CSRB) {
        int e = blockIdx.x * 256 + threadIdx.x;
        if (e < NN && out_size >= DENSE + MASKN) {
            int b = batch[e];
            out[DENSE + b*MAXA + (e - g_ptr[b])] = 1.0f;
        }
        if (e >= EE) return;
        int r = conn[e];
        int c = conn[EE + e];
        int slot = atomicAdd(&g_cursor[c], 1);
        g_csr_src[slot] = r;
        return;
    }

    int tid = threadIdx.x;
    for (int i = tid; i < FEAT*DD; i += 256) sW[i] = Wexp[i];
    if (tid < DD) sb[tid] = bexp[tid];
    __syncthreads();

    int nb   = blockIdx.x - CSRB;
    int wid  = tid >> 5;
    int lane = tid & 31;
    int n    = nb * 8 + wid;
    if (n >= NN) return;

    float la = 0.f;
    if (lane < FEAT) la = logf(atoms[n*FEAT + lane] + 1.0f);

    int d0 = lane * 4;
    float acc[4];
    #pragma unroll
    for (int q = 0; q < 4; q++) acc[q] = sb[d0 + q];
    #pragma unroll
    for (int f = 0; f < FEAT; f++) {
        float lf = __shfl_sync(0xffffffffu, la, f);
        #pragma unroll
        for (int q = 0; q < 4; q++)
            acc[q] = fmaf(lf, sW[f*DD + d0 + q], acc[q]);
    }
    float di = g_dinv[n];
    __half2 h0 = __floats2half2_rn(acc[0]*di, acc[1]*di);
    __half2 h1 = __floats2half2_rn(acc[2]*di, acc[3]*di);
    uint2 p;
    p.x = *reinterpret_cast<uint32_t*>(&h0);
    p.y = *reinterpret_cast<uint32_t*>(&h1);
    reinterpret_cast<uint2*>(g_y)[n*32 + lane] = p;
}

// ------- aggregation: agg[w] = dinv[w]*(sum_src y[src] + 2*y[w]), emitted fp16 -------
__global__ void k_agg(const __half* __restrict__ y)
{
    int w = (blockIdx.x * blockDim.x + threadIdx.x) >> 5;
    if (w >= NN) return;
    int lane = threadIdx.x & 31;
    const uint2* yr = reinterpret_cast<const uint2*>(y);

    uint2 sv = yr[w*32 + lane];
    float2 s0 = __half22float2(*reinterpret_cast<__half2*>(&sv.x));
    float2 s1 = __half22float2(*reinterpret_cast<__half2*>(&sv.y));
    float4 acc = make_float4(2.f*s0.x, 2.f*s0.y, 2.f*s1.x, 2.f*s1.y);

    int s = g_rowstart[w];
    int e = g_rowstart[w+1];
    int j = s;
    for (; j + 4 <= e; j += 4) {
        int   i0 = g_csr_src[j],   i1 = g_csr_src[j+1];
        int   i2 = g_csr_src[j+2], i3 = g_csr_src[j+3];
        uint2 u0 = yr[i0*32 + lane];
        uint2 u1 = yr[i1*32 + lane];
        uint2 u2 = yr[i2*32 + lane];
        uint2 u3 = yr[i3*32 + lane];
        float2 a0 = __half22float2(*reinterpret_cast<__half2*>(&u0.x));
        float2 b0 = __half22float2(*reinterpret_cast<__half2*>(&u0.y));
        float2 a1 = __half22float2(*reinterpret_cast<__half2*>(&u1.x));
        float2 b1 = __half22float2(*reinterpret_cast<__half2*>(&u1.y));
        float2 a2 = __half22float2(*reinterpret_cast<__half2*>(&u2.x));
        float2 b2 = __half22float2(*reinterpret_cast<__half2*>(&u2.y));
        float2 a3 = __half22float2(*reinterpret_cast<__half2*>(&u3.x));
        float2 b3 = __half22float2(*reinterpret_cast<__half2*>(&u3.y));
        acc.x += a0.x + a1.x + a2.x + a3.x;
        acc.y += a0.y + a1.y + a2.y + a3.y;
        acc.z += b0.x + b1.x + b2.x + b3.x;
        acc.w += b0.y + b1.y + b2.y + b3.y;
    }
    for (; j < e; j++) {
        int   src = g_csr_src[j];
        uint2 u   = yr[src*32 + lane];
        float2 a  = __half22float2(*reinterpret_cast<__half2*>(&u.x));
        float2 b  = __half22float2(*reinterpret_cast<__half2*>(&u.y));
        acc.x += a.x; acc.y += a.y; acc.z += b.x; acc.w += b.y;
    }

    float di = g_dinv[w];
    __half2 h0 = __floats2half2_rn(acc.x*di, acc.y*di);
    __half2 h1 = __floats2half2_rn(acc.z*di, acc.w*di);
    uint2 p;
    p.x = *reinterpret_cast<uint32_t*>(&h0);
    p.y = *reinterpret_cast<uint32_t*>(&h1);
    reinterpret_cast<uint2*>(g_apk)[w*32 + lane] = p;
}

// ---------------- fp16 mma.sync GEMM (single term): relu(A W^T + b) ----------------
__device__ __forceinline__ void mma_f16(float* d, const uint32_t* a, const uint32_t* b)
{
    asm volatile(
        "mma.sync.aligned.m16n8k16.row.col.f32.f16.f16.f32 "
        "{%0,%1,%2,%3}, {%4,%5,%6,%7}, {%8,%9}, {%0,%1,%2,%3};"
        : "+f"(d[0]), "+f"(d[1]), "+f"(d[2]), "+f"(d[3])
        : "r"(a[0]), "r"(a[1]), "r"(a[2]), "r"(a[3]), "r"(b[0]), "r"(b[1]));
}

// non-LAST: writes y = dinv*relu(..) as fp16. LAST: scatters fp32 into dense out.
template<bool LAST>
__global__ __launch_bounds__(256)
void k_gemm_mma(const __half* __restrict__ apk,
                const __half* __restrict__ wpk,
                const float* __restrict__ bias,
                __half* __restrict__ yout,
                float* __restrict__ dout,
                const int* __restrict__ batch)
{
    int tid    = threadIdx.x;
    int lane   = tid & 31;
    int wid    = tid >> 5;
    int warp_m = wid & 3;
    int warp_n = wid >> 2;
    int g      = lane >> 2;
    int tq     = lane & 3;

    int rowBase = blockIdx.x * TILE_M + warp_m * 32;
    int colBase = warp_n * 64;

    const uint32_t* AP = reinterpret_cast<const uint32_t*>(apk);   // 64 words per row
    const uint2*    BP = reinterpret_cast<const uint2*>(wpk);      // 32 fragment pairs per row

    const uint32_t* a0 = AP + (rowBase + g     ) * 64;
    const uint32_t* a1 = AP + (rowBase + g +  8) * 64;
    const uint32_t* a2 = AP + (rowBase + g + 16) * 64;
    const uint32_t* a3 = AP + (rowBase + g + 24) * 64;
    const uint2*    bp = BP + (colBase + g) * 32;      // row stride = 32 uint2

    float d[2][8][4];
    #pragma unroll
    for (int mt = 0; mt < 2; mt++)
        #pragma unroll
        for (int nt = 0; nt < 8; nt++)
            #pragma unroll
            for (int q = 0; q < 4; q++) d[mt][nt][q] = 0.0f;

    #pragma unroll 4
    for (int ks = 0; ks < 8; ks++) {
        int o0 = ks*8 + tq;
        int o1 = o0 + 4;

        uint32_t aF[2][4];
        aF[0][0] = a0[o0]; aF[0][1] = a1[o0]; aF[0][2] = a0[o1]; aF[0][3] = a1[o1];
        aF[1][0] = a2[o0]; aF[1][1] = a3[o0]; aF[1][2] = a2[o1]; aF[1][3] = a3[o1];

        uint32_t bF[8][2];
        #pragma unroll
        for (int nt = 0; nt < 8; nt++) {
            uint2 wv = bp[nt*256 + ks*4 + tq];   // 8*32=256 uint2 per 8 rows
            bF[nt][0] = wv.x; bF[nt][1] = wv.y;
        }
        #pragma unroll
        for (int mt = 0; mt < 2; mt++)
            #pragma unroll
            for (int nt = 0; nt < 8; nt++)
                mma_f16(d[mt][nt], aF[mt], bF[nt]);
    }

    #pragma unroll
    for (int mt = 0; mt < 2; mt++) {
        int m0 = rowBase + mt*16 + g;
        int m1 = m0 + 8;
        if (LAST) {
            int or0 = 0, or1 = 0;
            if (m0 < NN) { int b = batch[m0]; or0 = b*MAXA + (m0 - g_ptr[b]); }
            if (m1 < NN) { int b = batch[m1]; or1 = b*MAXA + (m1 - g_ptr[b]); }
            #pragma unroll
            for (int nt = 0; nt < 8; nt++) {
                int cn = colBase + nt*8 + tq*2;
                float2 bv = *reinterpret_cast<const float2*>(bias + cn);
                if (m0 < NN) {
                    float2 o;
                    o.x = fmaxf(d[mt][nt][0] + bv.x, 0.f);
                    o.y = fmaxf(d[mt][nt][1] + bv.y, 0.f);
                    *reinterpret_cast<float2*>(dout + or0*DD + cn) = o;
                }
                if (m1 < NN) {
                    float2 o;
                    o.x = fmaxf(d[mt][nt][2] + bv.x, 0.f);
                    o.y = fmaxf(d[mt][nt][3] + bv.y, 0.f);
                    *reinterpret_cast<float2*>(dout + or1*DD + cn) = o;
                }
            }
        } else {
            float di0 = (m0 < NN) ? g_dinv[m0] : 0.f;
            float di1 = (m1 < NN) ? g_dinv[m1] : 0.f;
            #pragma unroll
            for (int nt = 0; nt < 8; nt++) {
                int cn = colBase + nt*8 + tq*2;
                float2 bv = *reinterpret_cast<const float2*>(bias + cn);
                if (m0 < NN) {
                    float ox = fmaxf(d[mt][nt][0] + bv.x, 0.f) * di0;
                    float oy = fmaxf(d[mt][nt][1] + bv.y, 0.f) * di0;
                    *reinterpret_cast<__half2*>(yout + m0*DD + cn) = __floats2half2_rn(ox, oy);
                }
                if (m1 < NN) {
                    float ox = fmaxf(d[mt][nt][2] + bv.x, 0.f) * di1;
                    float oy = fmaxf(d[mt][nt][3] + bv.y, 0.f) * di1;
                    *reinterpret_cast<__half2*>(yout + m1*DD + cn) = __floats2half2_rn(ox, oy);
                }
            }
        }
    }
}

// ---------------- tail zero (only for any region beyond dense+mask) ----------------
__global__ void k_zero_tail(float* __restrict__ out, int start, int n)
{
    int i = blockIdx.x * blockDim.x + threadIdx.x;
    if (i < n) out[start + i] = 0.0f;
}

// ---------------- launch ----------------
extern "C" void kernel_launch(void* const* d_in, const int* in_sizes, int n_in,
                              void* d_out, int out_size)
{
    const float* atoms = (const float*)d_in[0];
    const int*   conn  = (const int*)d_in[1];
    const int*   batch = (const int*)d_in[2];
    const float* W_exp = (const float*)d_in[3];
    const float* b_exp = (const float*)d_in[4];
    const float* Ws    = (const float*)d_in[5];
    const float* bs    = (const float*)d_in[6];
    float* out = (float*)d_out;

    __half *py, *papk, *pwpk;
    cudaGetSymbolAddress((void**)&py,   g_y);
    cudaGetSymbolAddress((void**)&papk, g_apk);
    cudaGetSymbolAddress((void**)&pwpk, g_wpk);

    k_zero_prepw<<<ZB + PWB, 256>>>(Ws);
    k_hist<<<(EE + 255)/256, 256>>>(conn + EE, batch);
    k_scan1<<<SCAN_NB, SCAN_BS>>>();
    k_scan3<<<SCAN_NB, SCAN_BS>>>();
    k_csr_expand<<<CSRB + EXPB, 256>>>(conn, batch, out, out_size, atoms, W_exp, b_exp);

    int tail = out_size - (DENSE + MASKN);
    if (tail > 0)
        k_zero_tail<<<(tail + 255)/256, 256>>>(out, DENSE + MASKN, tail);

    int aggBlocks = (NN*32 + 255)/256;
    for (int l = 0; l < NLAYERS - 1; l++) {
        k_agg<<<aggBlocks, 256>>>(py);
        k_gemm_mma<false><<<GEMM_NB, 256>>>(papk, pwpk + l*DD*DD, bs + l*DD, py, nullptr, batch);
    }
    k_agg<<<aggBlocks, 256>>>(py);
    k_gemm_mma<true><<<GEMM_NB, 256>>>(papk, pwpk + 4*DD*DD, bs + 4*DD, nullptr, out, batch);
}

// round 13
// speedup vs baseline: 1.1387x; 1.0076x over previous
#include <cuda_runtime.h>
#include <cuda_fp16.h>
#include <cstdint>

#define NN   50000
#define EE   600000
#define FEAT 11
#define DD   128
#define BBATCH 500
#define MAXA 100
#define NLAYERS 5
#define DENSE (BBATCH*MAXA*DD)   /* 6,400,000 */
#define MASKN (BBATCH*MAXA)      /* 50,000 */

#define SCAN_BS   1024
#define SCAN_NB   ((NN + SCAN_BS - 1) / SCAN_BS)   /* 49 */
#define SCAN_FLAG (1 << 30)

#define TILE_M    128
#define GEMM_NB   ((NN + TILE_M - 1) / TILE_M)     /* 391 */
#define NNP       (GEMM_NB * TILE_M)               /* 50048, padded */

// merged-kernel block ranges
#define PWB  ((NLAYERS*DD*DD + 255)/256)           /* 320  prepw blocks  */
#define HB   ((EE + 255)/256)                      /* 2344 hist blocks   */
#define CSRB ((EE + 255)/256)                      /* 2344 csr blocks    */
#define EXPB ((NN + 7)/8)                          /* 6250 expand blocks */

// -------- scratch (static device globals; zero-initialized, no runtime alloc) --------
// INVARIANT maintained across graph replays: g_deg == 0, g_counts == 0, g_bsum == 0
// at kernel_launch entry (zero-init covers the first call; kernels below re-zero
// after consuming).
__device__ __half g_y[NN*DD];                  // y = dinv * x, fp16 (12.8 MB)
__device__ __half g_apk[NNP*DD];               // aggregated A, fp16 (12.8 MB; pad rows stay 0)
__device__ __half g_wpk[NLAYERS*DD*DD];        // Wt [l][n][k] fp16, fragment-paired word order
__device__ float g_dinv[NN];
__device__ int   g_deg[NN];
__device__ int   g_rowstart[NN+1];
__device__ int   g_cursor[NN];
__device__ int   g_csr_src[EE];
__device__ int   g_counts[BBATCH];
__device__ int   g_ptr[BBATCH];
__device__ int   g_bsum[SCAN_NB];

// ---------------- prep: W transpose + degree/count histogram (merged) ----------------
// W row layout (per n, 128 fp16 = 64 words): word w (=k>>1) stored at
// pair index p = (w>>3)*4 + (w&3), component c = (w>>2)&1 — one 8B load at
// pair index ks*4+tq yields the mma b-fragment {k16.lo, k16.hi}.
__global__ void k_prep_hist(const float* __restrict__ Ws,
                            const int* __restrict__ col, const int* __restrict__ batch)
{
    if (blockIdx.x < PWB) {
        int idx = blockIdx.x * 256 + threadIdx.x;
        if (idx >= NLAYERS*DD*DD) return;
        int l = idx >> 14;
        int r = idx & 16383;
        int n = r >> 7;
        int k = r & 127;
        float v = Ws[l*DD*DD + k*DD + n];
        int w = k >> 1;
        int p = ((w >> 3) << 2) | (w & 3);
        int c = (w >> 2) & 1;
        int dst = (l*DD + n) * DD + p*4 + c*2 + (k & 1);
        g_wpk[dst] = __float2half_rn(v);
        return;
    }
    int i = (blockIdx.x - PWB) * 256 + threadIdx.x;
    if (i < EE) atomicAdd(&g_deg[col[i]], 1);
    if (i < NN) atomicAdd(&g_counts[batch[i]], 1);
}

// -------- fused scan: local scan + flagged publish + predecessor poll + apply --------
// 49 blocks <= 148 SMs -> all resident in wave 1, spin-poll is deadlock-free.
__global__ __launch_bounds__(SCAN_BS)
void k_scan()
{
    __shared__ int warp_sums[32];
    __shared__ int s_boff;
    int tid  = threadIdx.x;
    int lane = tid & 31;
    int wid  = tid >> 5;
    int i    = blockIdx.x * SCAN_BS + tid;

    int v0 = (i < NN) ? g_deg[i] : 0;
    if (i < NN) {
        g_dinv[i] = rsqrtf((float)v0 + 2.0f);
        g_deg[i]  = 0;                       // restore invariant for next replay
    }
    int v  = v0;
    #pragma unroll
    for (int off = 1; off < 32; off <<= 1) {
        int t = __shfl_up_sync(0xffffffffu, v, off);
        if (lane >= off) v += t;
    }
    if (lane == 31) warp_sums[wid] = v;
    __syncthreads();
    if (wid == 0) {
        int s = warp_sums[lane];
        #pragma unroll
        for (int off = 1; off < 32; off <<= 1) {
            int t = __shfl_up_sync(0xffffffffu, s, off);
            if (lane >= off) s += t;
        }
        warp_sums[lane] = s;
    }
    __syncthreads();
    int incl = v + (wid ? warp_sums[wid-1] : 0);

    // publish this block's aggregate (total = warp_sums[31])
    if (tid == 0) {
        int total = warp_sums[31];
        atomicExch(&g_bsum[blockIdx.x], total | SCAN_FLAG);
    }

    // warp 1 polls predecessors and sums their aggregates
    if (wid == 1) {
        int sum = 0;
        for (int p = lane; p < blockIdx.x; p += 32) {
            int bv;
            do { bv = atomicAdd(&g_bsum[p], 0); } while (!(bv & SCAN_FLAG));
            sum += bv & ~SCAN_FLAG;
        }
        #pragma unroll
        for (int off = 16; off > 0; off >>= 1)
            sum += __shfl_down_sync(0xffffffffu, sum, off);
        if (lane == 0) s_boff = sum;
    }
    __syncthreads();
    int boff = s_boff;

    if (i < NN) {
        g_rowstart[i+1] = incl + boff;
        g_cursor[i]     = incl - v0 + boff;
    }

    if (blockIdx.x == 0) {
        if (tid == 0) g_rowstart[0] = 0;
        // exclusive scan counts[500] -> ptr, then re-zero counts
        int c = (tid < BBATCH) ? g_counts[tid] : 0;
        int vv = c;
        #pragma unroll
        for (int off = 1; off < 32; off <<= 1) {
            int t = __shfl_up_sync(0xffffffffu, vv, off);
            if (lane >= off) vv += t;
        }
        __syncthreads();          // warp_sums reuse barrier
        if (lane == 31) warp_sums[wid] = vv;
        __syncthreads();
        if (wid == 0) {
            int s = warp_sums[lane];
            #pragma unroll
            for (int off = 1; off < 32; off <<= 1) {
                int t = __shfl_up_sync(0xffffffffu, s, off);
                if (lane >= off) s += t;
            }
            warp_sums[lane] = s;
        }
        __syncthreads();
        int incl2 = vv + (wid ? warp_sums[wid-1] : 0);
        if (tid < BBATCH) {
            g_ptr[tid]    = incl2 - c;
            g_counts[tid] = 0;                // restore invariant
        }
    }
}

// ---- merged: csr build + mask write + log-expansion (+ g_bsum cleanup) ----
__global__ __launch_bounds__(256)
void k_csr_expand(const int* __restrict__ conn, const int* __restrict__ batch,
                  float* __restrict__ out, int out_size,
                  const float* __restrict__ atoms,
                  const float* __restrict__ Wexp,
                  const float* __restrict__ bexp)
{
    __shared__ float sW[FEAT*DD];
    __shared__ float sb[DD];

    if (blockIdx.x < CSRB) {
        int e = blockIdx.x * 256 + threadIdx.x;
        if (blockIdx.x == 0 && threadIdx.x < SCAN_NB)
            g_bsum[threadIdx.x] = 0;          // restore invariant
        if (e < NN && out_size >= DENSE + MASKN) {
            int b = batch[e];
            out[DENSE + b*MAXA + (e - g_ptr[b])] = 1.0f;
        }
        if (e >= EE) return;
        int r = conn[e];
        int c = conn[EE + e];
        int slot = atomicAdd(&g_cursor[c], 1);
        g_csr_src[slot] = r;
        return;
    }

    int tid = threadIdx.x;
    for (int i = tid; i < FEAT*DD; i += 256) sW[i] = Wexp[i];
    if (tid < DD) sb[tid] = bexp[tid];
    __syncthreads();

    int nb   = blockIdx.x - CSRB;
    int wid  = tid >> 5;
    int lane = tid & 31;
    int n    = nb * 8 + wid;
    if (n >= NN) return;

    float la = 0.f;
    if (lane < FEAT) la = logf(atoms[n*FEAT + lane] + 1.0f);

    int d0 = lane * 4;
    float acc[4];
    #pragma unroll
    for (int q = 0; q < 4; q++) acc[q] = sb[d0 + q];
    #pragma unroll
    for (int f = 0; f < FEAT; f++) {
        float lf = __shfl_sync(0xffffffffu, la, f);
        #pragma unroll
        for (int q = 0; q < 4; q++)
            acc[q] = fmaf(lf, sW[f*DD + d0 + q], acc[q]);
    }
    float di = g_dinv[n];
    __half2 h0 = __floats2half2_rn(acc[0]*di, acc[1]*di);
    __half2 h1 = __floats2half2_rn(acc[2]*di, acc[3]*di);
    uint2 p;
    p.x = *reinterpret_cast<uint32_t*>(&h0);
    p.y = *reinterpret_cast<uint32_t*>(&h1);
    reinterpret_cast<uint2*>(g_y)[n*32 + lane] = p;
}

// ------- aggregation: agg[w] = dinv[w]*(sum_src y[src] + 2*y[w]), emitted fp16 -------
__global__ void k_agg(const __half* __restrict__ y)
{
    int w = (blockIdx.x * blockDim.x + threadIdx.x) >> 5;
    if (w >= NN) return;
    int lane = threadIdx.x & 31;
    const uint2* yr = reinterpret_cast<const uint2*>(y);

    uint2 sv = yr[w*32 + lane];
    float2 s0 = __half22float2(*reinterpret_cast<__half2*>(&sv.x));
    float2 s1 = __half22float2(*reinterpret_cast<__half2*>(&sv.y));
    float4 acc = make_float4(2.f*s0.x, 2.f*s0.y, 2.f*s1.x, 2.f*s1.y);

    int s = g_rowstart[w];
    int e = g_rowstart[w+1];
    int j = s;
    for (; j + 4 <= e; j += 4) {
        int   i0 = g_csr_src[j],   i1 = g_csr_src[j+1];
        int   i2 = g_csr_src[j+2], i3 = g_csr_src[j+3];
        uint2 u0 = yr[i0*32 + lane];
        uint2 u1 = yr[i1*32 + lane];
        uint2 u2 = yr[i2*32 + lane];
        uint2 u3 = yr[i3*32 + lane];
        float2 a0 = __half22float2(*reinterpret_cast<__half2*>(&u0.x));
        float2 b0 = __half22float2(*reinterpret_cast<__half2*>(&u0.y));
        float2 a1 = __half22float2(*reinterpret_cast<__half2*>(&u1.x));
        float2 b1 = __half22float2(*reinterpret_cast<__half2*>(&u1.y));
        float2 a2 = __half22float2(*reinterpret_cast<__half2*>(&u2.x));
        float2 b2 = __half22float2(*reinterpret_cast<__half2*>(&u2.y));
        float2 a3 = __half22float2(*reinterpret_cast<__half2*>(&u3.x));
        float2 b3 = __half22float2(*reinterpret_cast<__half2*>(&u3.y));
        acc.x += a0.x + a1.x + a2.x + a3.x;
        acc.y += a0.y + a1.y + a2.y + a3.y;
        acc.z += b0.x + b1.x + b2.x + b3.x;
        acc.w += b0.y + b1.y + b2.y + b3.y;
    }
    for (; j < e; j++) {
        int   src = g_csr_src[j];
        uint2 u   = yr[src*32 + lane];
        float2 a  = __half22float2(*reinterpret_cast<__half2*>(&u.x));
        float2 b  = __half22float2(*reinterpret_cast<__half2*>(&u.y));
        acc.x += a.x; acc.y += a.y; acc.z += b.x; acc.w += b.y;
    }

    float di = g_dinv[w];
    __half2 h0 = __floats2half2_rn(acc.x*di, acc.y*di);
    __half2 h1 = __floats2half2_rn(acc.z*di, acc.w*di);
    uint2 p;
    p.x = *reinterpret_cast<uint32_t*>(&h0);
    p.y = *reinterpret_cast<uint32_t*>(&h1);
    reinterpret_cast<uint2*>(g_apk)[w*32 + lane] = p;
}

// ---------------- fp16 mma.sync GEMM (single term): relu(A W^T + b) ----------------
__device__ __forceinline__ void mma_f16(float* d, const uint32_t* a, const uint32_t* b)
{
    asm volatile(
        "mma.sync.aligned.m16n8k16.row.col.f32.f16.f16.f32 "
        "{%0,%1,%2,%3}, {%4,%5,%6,%7}, {%8,%9}, {%0,%1,%2,%3};"
        : "+f"(d[0]), "+f"(d[1]), "+f"(d[2]), "+f"(d[3])
        : "r"(a[0]), "r"(a[1]), "r"(a[2]), "r"(a[3]), "r"(b[0]), "r"(b[1]));
}

// non-LAST: writes y = dinv*relu(..) as fp16. LAST: scatters fp32 into dense out.
template<bool LAST>
__global__ __launch_bounds__(256)
void k_gemm_mma(const __half* __restrict__ apk,
                const __half* __restrict__ wpk,
                const float* __restrict__ bias,
                __half* __restrict__ yout,
                float* __restrict__ dout,
                const int* __restrict__ batch)
{
    int tid    = threadIdx.x;
    int lane   = tid & 31;
    int wid    = tid >> 5;
    int warp_m = wid & 3;
    int warp_n = wid >> 2;
    int g      = lane >> 2;
    int tq     = lane & 3;

    int rowBase = blockIdx.x * TILE_M + warp_m * 32;
    int colBase = warp_n * 64;

    const uint32_t* AP = reinterpret_cast<const uint32_t*>(apk);   // 64 words per row
    const uint2*    BP = reinterpret_cast<const uint2*>(wpk);      // 32 fragment pairs per row

    const uint32_t* a0 = AP + (rowBase + g     ) * 64;
    const uint32_t* a1 = AP + (rowBase + g +  8) * 64;
    const uint32_t* a2 = AP + (rowBase + g + 16) * 64;
    const uint32_t* a3 = AP + (rowBase + g + 24) * 64;
    const uint2*    bp = BP + (colBase + g) * 32;

    float d[2][8][4];
    #pragma unroll
    for (int mt = 0; mt < 2; mt++)
        #pragma unroll
        for (int nt = 0; nt < 8; nt++)
            #pragma unroll
            for (int q = 0; q < 4; q++) d[mt][nt][q] = 0.0f;

    #pragma unroll 4
    for (int ks = 0; ks < 8; ks++) {
        int o0 = ks*8 + tq;
        int o1 = o0 + 4;

        uint32_t aF[2][4];
        aF[0][0] = a0[o0]; aF[0][1] = a1[o0]; aF[0][2] = a0[o1]; aF[0][3] = a1[o1];
        aF[1][0] = a2[o0]; aF[1][1] = a3[o0]; aF[1][2] = a2[o1]; aF[1][3] = a3[o1];

        uint32_t bF[8][2];
        #pragma unroll
        for (int nt = 0; nt < 8; nt++) {
            uint2 wv = bp[nt*256 + ks*4 + tq];
            bF[nt][0] = wv.x; bF[nt][1] = wv.y;
        }
        #pragma unroll
        for (int mt = 0; mt < 2; mt++)
            #pragma unroll
            for (int nt = 0; nt < 8; nt++)
                mma_f16(d[mt][nt], aF[mt], bF[nt]);
    }

    #pragma unroll
    for (int mt = 0; mt < 2; mt++) {
        int m0 = rowBase + mt*16 + g;
        int m1 = m0 + 8;
        if (LAST) {
            int or0 = 0, or1 = 0;
            if (m0 < NN) { int b = batch[m0]; or0 = b*MAXA + (m0 - g_ptr[b]); }
            if (m1 < NN) { int b = batch[m1]; or1 = b*MAXA + (m1 - g_ptr[b]); }
            #pragma unroll
            for (int nt = 0; nt < 8; nt++) {
                int cn = colBase + nt*8 + tq*2;
                float2 bv = *reinterpret_cast<const float2*>(bias + cn);
                if (m0 < NN) {
                    float2 o;
                    o.x = fmaxf(d[mt][nt][0] + bv.x, 0.f);
                    o.y = fmaxf(d[mt][nt][1] + bv.y, 0.f);
                    *reinterpret_cast<float2*>(dout + or0*DD + cn) = o;
                }
                if (m1 < NN) {
                    float2 o;
                    o.x = fmaxf(d[mt][nt][2] + bv.x, 0.f);
                    o.y = fmaxf(d[mt][nt][3] + bv.y, 0.f);
                    *reinterpret_cast<float2*>(dout + or1*DD + cn) = o;
                }
            }
        } else {
            float di0 = (m0 < NN) ? g_dinv[m0] : 0.f;
            float di1 = (m1 < NN) ? g_dinv[m1] : 0.f;
            #pragma unroll
            for (int nt = 0; nt < 8; nt++) {
                int cn = colBase + nt*8 + tq*2;
                float2 bv = *reinterpret_cast<const float2*>(bias + cn);
                if (m0 < NN) {
                    float ox = fmaxf(d[mt][nt][0] + bv.x, 0.f) * di0;
                    float oy = fmaxf(d[mt][nt][1] + bv.y, 0.f) * di0;
                    *reinterpret_cast<__half2*>(yout + m0*DD + cn) = __floats2half2_rn(ox, oy);
                }
                if (m1 < NN) {
                    float ox = fmaxf(d[mt][nt][2] + bv.x, 0.f) * di1;
                    float oy = fmaxf(d[mt][nt][3] + bv.y, 0.f) * di1;
                    *reinterpret_cast<__half2*>(yout + m1*DD + cn) = __floats2half2_rn(ox, oy);
                }
            }
        }
    }
}

// ---------------- tail zero (only for any region beyond dense+mask) ----------------
__global__ void k_zero_tail(float* __restrict__ out, int start, int n)
{
    int i = blockIdx.x * blockDim.x + threadIdx.x;
    if (i < n) out[start + i] = 0.0f;
}

// ---------------- launch ----------------
extern "C" void kernel_launch(void* const* d_in, const int* in_sizes, int n_in,
                              void* d_out, int out_size)
{
    const float* atoms = (const float*)d_in[0];
    const int*   conn  = (const int*)d_in[1];
    const int*   batch = (const int*)d_in[2];
    const float* W_exp = (const float*)d_in[3];
    const float* b_exp = (const float*)d_in[4];
    const float* Ws    = (const float*)d_in[5];
    const float* bs    = (const float*)d_in[6];
    float* out = (float*)d_out;

    __half *py, *papk, *pwpk;
    cudaGetSymbolAddress((void**)&py,   g_y);
    cudaGetSymbolAddress((void**)&papk, g_apk);
    cudaGetSymbolAddress((void**)&pwpk, g_wpk);

    k_prep_hist<<<PWB + HB, 256>>>(Ws, conn + EE, batch);
    k_scan<<<SCAN_NB, SCAN_BS>>>();
    k_csr_expand<<<CSRB + EXPB, 256>>>(conn, batch, out, out_size, atoms, W_exp, b_exp);

    int tail = out_size - (DENSE + MASKN);
    if (tail > 0)
        k_zero_tail<<<(tail + 255)/256, 256>>>(out, DENSE + MASKN, tail);

    int aggBlocks = (NN*32 + 255)/256;
    for (int l = 0; l < NLAYERS - 1; l++) {
        k_agg<<<aggBlocks, 256>>>(py);
        k_gemm_mma<false><<<GEMM_NB, 256>>>(papk, pwpk + l*DD*DD, bs + l*DD, py, nullptr, batch);
    }
    k_agg<<<aggBlocks, 256>>>(py);
    k_gemm_mma<true><<<GEMM_NB, 256>>>(papk, pwpk + 4*DD*DD, bs + 4*DD, nullptr, out, batch);
}

// round 14
// speedup vs baseline: 1.1581x; 1.0171x over previous
#include <cuda_runtime.h>
#include <cuda_fp16.h>
#include <cstdint>

#define NN   50000
#define EE   600000
#define FEAT 11
#define DD   128
#define BBATCH 500
#define MAXA 100
#define NLAYERS 5
#define DENSE (BBATCH*MAXA*DD)   /* 6,400,000 */
#define MASKN (BBATCH*MAXA)      /* 50,000 */

#define SCAN_BS   1024
#define SCAN_NB   ((NN + SCAN_BS - 1) / SCAN_BS)   /* 49 */
#define SCAN_FLAG (1 << 30)

#define TILE_M    128
#define GEMM_NB   ((NN + TILE_M - 1) / TILE_M)     /* 391 */
#define NNP       (GEMM_NB * TILE_M)               /* 50048, padded */

// merged-kernel block ranges
#define PWB  ((NLAYERS*DD*DD + 255)/256)           /* 320  prepw blocks  */
#define HB   ((EE + 255)/256)                      /* 2344 hist blocks   */
#define CSRB ((EE + 255)/256)                      /* 2344 csr blocks    */
#define EXPB ((NN + 7)/8)                          /* 6250 expand blocks */

// -------- scratch (static device globals; zero-initialized, no runtime alloc) --------
// INVARIANT maintained across graph replays: g_deg == 0, g_counts == 0, g_bsum == 0
// at kernel_launch entry.
__device__ __half g_y[NN*DD];                  // y = dinv * x, fp16 (12.8 MB)
__device__ __half g_apk[NNP*DD];               // aggregated A, fp16 (12.8 MB; pad rows stay 0)
__device__ __half g_wpk[NLAYERS*DD*DD];        // Wt [l][n][k] fp16, fragment-paired word order
__device__ float g_dinv[NN];
__device__ int   g_deg[NN];
__device__ int   g_rowstart[NN+1];
__device__ int   g_cursor[NN];
__device__ int   g_csr_src[EE];
__device__ int   g_counts[BBATCH];
__device__ int   g_ptr[BBATCH];
__device__ int   g_bsum[SCAN_NB];

// ---------------- prep: W transpose + degree/count histogram (merged) ----------------
__global__ void k_prep_hist(const float* __restrict__ Ws,
                            const int* __restrict__ col, const int* __restrict__ batch)
{
    if (blockIdx.x < PWB) {
        int idx = blockIdx.x * 256 + threadIdx.x;
        if (idx >= NLAYERS*DD*DD) return;
        int l = idx >> 14;
        int r = idx & 16383;
        int n = r >> 7;
        int k = r & 127;
        float v = Ws[l*DD*DD + k*DD + n];
        int w = k >> 1;
        int p = ((w >> 3) << 2) | (w & 3);
        int c = (w >> 2) & 1;
        int dst = (l*DD + n) * DD + p*4 + c*2 + (k & 1);
        g_wpk[dst] = __float2half_rn(v);
        return;
    }
    int i = (blockIdx.x - PWB) * 256 + threadIdx.x;
    if (i < EE) atomicAdd(&g_deg[col[i]], 1);
    if (i < NN) atomicAdd(&g_counts[batch[i]], 1);
}

// -------- fused scan: local scan + flagged publish + predecessor poll + apply --------
__global__ __launch_bounds__(SCAN_BS)
void k_scan()
{
    __shared__ int warp_sums[32];
    __shared__ int s_boff;
    int tid  = threadIdx.x;
    int lane = tid & 31;
    int wid  = tid >> 5;
    int i    = blockIdx.x * SCAN_BS + tid;

    int v0 = (i < NN) ? g_deg[i] : 0;
    if (i < NN) {
        g_dinv[i] = rsqrtf((float)v0 + 2.0f);
        g_deg[i]  = 0;                       // restore invariant for next replay
    }
    int v  = v0;
    #pragma unroll
    for (int off = 1; off < 32; off <<= 1) {
        int t = __shfl_up_sync(0xffffffffu, v, off);
        if (lane >= off) v += t;
    }
    if (lane == 31) warp_sums[wid] = v;
    __syncthreads();
    if (wid == 0) {
        int s = warp_sums[lane];
        #pragma unroll
        for (int off = 1; off < 32; off <<= 1) {
            int t = __shfl_up_sync(0xffffffffu, s, off);
            if (lane >= off) s += t;
        }
        warp_sums[lane] = s;
    }
    __syncthreads();
    int incl = v + (wid ? warp_sums[wid-1] : 0);

    if (tid == 0) {
        int total = warp_sums[31];
        atomicExch(&g_bsum[blockIdx.x], total | SCAN_FLAG);
    }

    if (wid == 1) {
        int sum = 0;
        for (int p = lane; p < blockIdx.x; p += 32) {
            int bv;
            do { bv = atomicAdd(&g_bsum[p], 0); } while (!(bv & SCAN_FLAG));
            sum += bv & ~SCAN_FLAG;
        }
        #pragma unroll
        for (int off = 16; off > 0; off >>= 1)
            sum += __shfl_down_sync(0xffffffffu, sum, off);
        if (lane == 0) s_boff = sum;
    }
    __syncthreads();
    int boff = s_boff;

    if (i < NN) {
        g_rowstart[i+1] = incl + boff;
        g_cursor[i]     = incl - v0 + boff;
    }

    if (blockIdx.x == 0) {
        if (tid == 0) g_rowstart[0] = 0;
        int c = (tid < BBATCH) ? g_counts[tid] : 0;
        int vv = c;
        #pragma unroll
        for (int off = 1; off < 32; off <<= 1) {
            int t = __shfl_up_sync(0xffffffffu, vv, off);
            if (lane >= off) vv += t;
        }
        __syncthreads();
        if (lane == 31) warp_sums[wid] = vv;
        __syncthreads();
        if (wid == 0) {
            int s = warp_sums[lane];
            #pragma unroll
            for (int off = 1; off < 32; off <<= 1) {
                int t = __shfl_up_sync(0xffffffffu, s, off);
                if (lane >= off) s += t;
            }
            warp_sums[lane] = s;
        }
        __syncthreads();
        int incl2 = vv + (wid ? warp_sums[wid-1] : 0);
        if (tid < BBATCH) {
            g_ptr[tid]    = incl2 - c;
            g_counts[tid] = 0;
        }
    }
}

// ---- merged: csr build + mask write + log-expansion (+ g_bsum cleanup) ----
__global__ __launch_bounds__(256)
void k_csr_expand(const int* __restrict__ conn, const int* __restrict__ batch,
                  float* __restrict__ out, int out_size,
                  const float* __restrict__ atoms,
                  const float* __restrict__ Wexp,
                  const float* __restrict__ bexp)
{
    __shared__ float sW[FEAT*DD];
    __shared__ float sb[DD];

    if (blockIdx.x < CSRB) {
        int e = blockIdx.x * 256 + threadIdx.x;
        if (blockIdx.x == 0 && threadIdx.x < SCAN_NB)
            g_bsum[threadIdx.x] = 0;
        if (e < NN && out_size >= DENSE + MASKN) {
            int b = batch[e];
            out[DENSE + b*MAXA + (e - g_ptr[b])] = 1.0f;
        }
        if (e >= EE) return;
        int r = conn[e];
        int c = conn[EE + e];
        int slot = atomicAdd(&g_cursor[c], 1);
        g_csr_src[slot] = r;
        return;
    }

    int tid = threadIdx.x;
    for (int i = tid; i < FEAT*DD; i += 256) sW[i] = Wexp[i];
    if (tid < DD) sb[tid] = bexp[tid];
    __syncthreads();

    int nb   = blockIdx.x - CSRB;
    int wid  = tid >> 5;
    int lane = tid & 31;
    int n    = nb * 8 + wid;
    if (n >= NN) return;

    float la = 0.f;
    if (lane < FEAT) la = logf(atoms[n*FEAT + lane] + 1.0f);

    int d0 = lane * 4;
    float acc[4];
    #pragma unroll
    for (int q = 0; q < 4; q++) acc[q] = sb[d0 + q];
    #pragma unroll
    for (int f = 0; f < FEAT; f++) {
        float lf = __shfl_sync(0xffffffffu, la, f);
        #pragma unroll
        for (int q = 0; q < 4; q++)
            acc[q] = fmaf(lf, sW[f*DD + d0 + q], acc[q]);
    }
    float di = g_dinv[n];
    __half2 h0 = __floats2half2_rn(acc[0]*di, acc[1]*di);
    __half2 h1 = __floats2half2_rn(acc[2]*di, acc[3]*di);
    uint2 p;
    p.x = *reinterpret_cast<uint32_t*>(&h0);
    p.y = *reinterpret_cast<uint32_t*>(&h1);
    reinterpret_cast<uint2*>(g_y)[n*32 + lane] = p;
}

// ------- aggregation: agg[w] = dinv[w]*(sum_src y[src] + 2*y[w]), MLP=8 gathers -------
__global__ void k_agg(const __half* __restrict__ y)
{
    int w = (blockIdx.x * blockDim.x + threadIdx.x) >> 5;
    if (w >= NN) return;
    int lane = threadIdx.x & 31;
    const uint2* yr = reinterpret_cast<const uint2*>(y);

    uint2 sv = yr[w*32 + lane];
    float2 s0 = __half22float2(*reinterpret_cast<__half2*>(&sv.x));
    float2 s1 = __half22float2(*reinterpret_cast<__half2*>(&sv.y));
    float4 acc = make_float4(2.f*s0.x, 2.f*s0.y, 2.f*s1.x, 2.f*s1.y);

    int s = g_rowstart[w];
    int e = g_rowstart[w+1];
    int j = s;

    // 8-deep batched gathers: 8 independent LDGs in flight per warp
    for (; j + 8 <= e; j += 8) {
        int idx[8];
        #pragma unroll
        for (int q = 0; q < 8; q++) idx[q] = g_csr_src[j + q];
        uint2 u[8];
        #pragma unroll
        for (int q = 0; q < 8; q++) u[q] = yr[idx[q]*32 + lane];
        #pragma unroll
        for (int q = 0; q < 8; q++) {
            float2 a = __half22float2(*reinterpret_cast<__half2*>(&u[q].x));
            float2 b = __half22float2(*reinterpret_cast<__half2*>(&u[q].y));
            acc.x += a.x; acc.y += a.y; acc.z += b.x; acc.w += b.y;
        }
    }
    for (; j + 4 <= e; j += 4) {
        int idx[4];
        #pragma unroll
        for (int q = 0; q < 4; q++) idx[q] = g_csr_src[j + q];
        uint2 u[4];
        #pragma unroll
        for (int q = 0; q < 4; q++) u[q] = yr[idx[q]*32 + lane];
        #pragma unroll
        for (int q = 0; q < 4; q++) {
            float2 a = __half22float2(*reinterpret_cast<__half2*>(&u[q].x));
            float2 b = __half22float2(*reinterpret_cast<__half2*>(&u[q].y));
            acc.x += a.x; acc.y += a.y; acc.z += b.x; acc.w += b.y;
        }
    }
    for (; j < e; j++) {
        int   src = g_csr_src[j];
        uint2 u   = yr[src*32 + lane];
        float2 a  = __half22float2(*reinterpret_cast<__half2*>(&u.x));
        float2 b  = __half22float2(*reinterpret_cast<__half2*>(&u.y));
        acc.x += a.x; acc.y += a.y; acc.z += b.x; acc.w += b.y;
    }

    float di = g_dinv[w];
    __half2 h0 = __floats2half2_rn(acc.x*di, acc.y*di);
    __half2 h1 = __floats2half2_rn(acc.z*di, acc.w*di);
    uint2 p;
    p.x = *reinterpret_cast<uint32_t*>(&h0);
    p.y = *reinterpret_cast<uint32_t*>(&h1);
    reinterpret_cast<uint2*>(g_apk)[w*32 + lane] = p;
}

// ---------------- fp16 mma.sync GEMM (single term): relu(A W^T + b) ----------------
__device__ __forceinline__ void mma_f16(float* d, const uint32_t* a, const uint32_t* b)
{
    asm volatile(
        "mma.sync.aligned.m16n8k16.row.col.f32.f16.f16.f32 "
        "{%0,%1,%2,%3}, {%4,%5,%6,%7}, {%8,%9}, {%0,%1,%2,%3};"
        : "+f"(d[0]), "+f"(d[1]), "+f"(d[2]), "+f"(d[3])
        : "r"(a[0]), "r"(a[1]), "r"(a[2]), "r"(a[3]), "r"(b[0]), "r"(b[1]));
}

// non-LAST: writes y = dinv*relu(..) as fp16. LAST: scatters fp32 into dense out.
template<bool LAST>
__global__ __launch_bounds__(256)
void k_gemm_mma(const __half* __restrict__ apk,
                const __half* __restrict__ wpk,
                const float* __restrict__ bias,
                __half* __restrict__ yout,
                float* __restrict__ dout,
                const int* __restrict__ batch)
{
    int tid    = threadIdx.x;
    int lane   = tid & 31;
    int wid    = tid >> 5;
    int warp_m = wid & 3;
    int warp_n = wid >> 2;
    int g      = lane >> 2;
    int tq     = lane & 3;

    int rowBase = blockIdx.x * TILE_M + warp_m * 32;
    int colBase = warp_n * 64;

    const uint32_t* AP = reinterpret_cast<const uint32_t*>(apk);
    const uint2*    BP = reinterpret_cast<const uint2*>(wpk);

    const uint32_t* a0 = AP + (rowBase + g     ) * 64;
    const uint32_t* a1 = AP + (rowBase + g +  8) * 64;
    const uint32_t* a2 = AP + (rowBase + g + 16) * 64;
    const uint32_t* a3 = AP + (rowBase + g + 24) * 64;
    const uint2*    bp = BP + (colBase + g) * 32;

    float d[2][8][4];
    #pragma unroll
    for (int mt = 0; mt < 2; mt++)
        #pragma unroll
        for (int nt = 0; nt < 8; nt++)
            #pragma unroll
            for (int q = 0; q < 4; q++) d[mt][nt][q] = 0.0f;

    #pragma unroll 4
    for (int ks = 0; ks < 8; ks++) {
        int o0 = ks*8 + tq;
        int o1 = o0 + 4;

        uint32_t aF[2][4];
        aF[0][0] = a0[o0]; aF[0][1] = a1[o0]; aF[0][2] = a0[o1]; aF[0][3] = a1[o1];
        aF[1][0] = a2[o0]; aF[1][1] = a3[o0]; aF[1][2] = a2[o1]; aF[1][3] = a3[o1];

        uint32_t bF[8][2];
        #pragma unroll
        for (int nt = 0; nt < 8; nt++) {
            uint2 wv = bp[nt*256 + ks*4 + tq];
            bF[nt][0] = wv.x; bF[nt][1] = wv.y;
        }
        #pragma unroll
        for (int mt = 0; mt < 2; mt++)
            #pragma unroll
            for (int nt = 0; nt < 8; nt++)
                mma_f16(d[mt][nt], aF[mt], bF[nt]);
    }

    #pragma unroll
    for (int mt = 0; mt < 2; mt++) {
        int m0 = rowBase + mt*16 + g;
        int m1 = m0 + 8;
        if (LAST) {
            int or0 = 0, or1 = 0;
            if (m0 < NN) { int b = batch[m0]; or0 = b*MAXA + (m0 - g_ptr[b]); }
            if (m1 < NN) { int b = batch[m1]; or1 = b*MAXA + (m1 - g_ptr[b]); }
            #pragma unroll
            for (int nt = 0; nt < 8; nt++) {
                int cn = colBase + nt*8 + tq*2;
                float2 bv = *reinterpret_cast<const float2*>(bias + cn);
                if (m0 < NN) {
                    float2 o;
                    o.x = fmaxf(d[mt][nt][0] + bv.x, 0.f);
                    o.y = fmaxf(d[mt][nt][1] + bv.y, 0.f);
                    *reinterpret_cast<float2*>(dout + or0*DD + cn) = o;
                }
                if (m1 < NN) {
                    float2 o;
                    o.x = fmaxf(d[mt][nt][2] + bv.x, 0.f);
                    o.y = fmaxf(d[mt][nt][3] + bv.y, 0.f);
                    *reinterpret_cast<float2*>(dout + or1*DD + cn) = o;
                }
            }
        } else {
            float di0 = (m0 < NN) ? g_dinv[m0] : 0.f;
            float di1 = (m1 < NN) ? g_dinv[m1] : 0.f;
            #pragma unroll
            for (int nt = 0; nt < 8; nt++) {
                int cn = colBase + nt*8 + tq*2;
                float2 bv = *reinterpret_cast<const float2*>(bias + cn);
                if (m0 < NN) {
                    float ox = fmaxf(d[mt][nt][0] + bv.x, 0.f) * di0;
                    float oy = fmaxf(d[mt][nt][1] + bv.y, 0.f) * di0;
                    *reinterpret_cast<__half2*>(yout + m0*DD + cn) = __floats2half2_rn(ox, oy);
                }
                if (m1 < NN) {
                    float ox = fmaxf(d[mt][nt][2] + bv.x, 0.f) * di1;
                    float oy = fmaxf(d[mt][nt][3] + bv.y, 0.f) * di1;
                    *reinterpret_cast<__half2*>(yout + m1*DD + cn) = __floats2half2_rn(ox, oy);
                }
            }
        }
    }
}

// ---------------- tail zero (only for any region beyond dense+mask) ----------------
__global__ void k_zero_tail(float* __restrict__ out, int start, int n)
{
    int i = blockIdx.x * blockDim.x + threadIdx.x;
    if (i < n) out[start + i] = 0.0f;
}

// ---------------- launch ----------------
extern "C" void kernel_launch(void* const* d_in, const int* in_sizes, int n_in,
                              void* d_out, int out_size)
{
    const float* atoms = (const float*)d_in[0];
    const int*   conn  = (const int*)d_in[1];
    const int*   batch = (const int*)d_in[2];
    const float* W_exp = (const float*)d_in[3];
    const float* b_exp = (const float*)d_in[4];
    const float* Ws    = (const float*)d_in[5];
    const float* bs    = (const float*)d_in[6];
    float* out = (float*)d_out;

    __half *py, *papk, *pwpk;
    cudaGetSymbolAddress((void**)&py,   g_y);
    cudaGetSymbolAddress((void**)&papk, g_apk);
    cudaGetSymbolAddress((void**)&pwpk, g_wpk);

    k_prep_hist<<<PWB + HB, 256>>>(Ws, conn + EE, batch);
    k_scan<<<SCAN_NB, SCAN_BS>>>();
    k_csr_expand<<<CSRB + EXPB, 256>>>(conn, batch, out, out_size, atoms, W_exp, b_exp);

    int tail = out_size - (DENSE + MASKN);
    if (tail > 0)
        k_zero_tail<<<(tail + 255)/256, 256>>>(out, DENSE + MASKN, tail);

    int aggBlocks = (NN*32 + 255)/256;
    for (int l = 0; l < NLAYERS - 1; l++) {
        k_agg<<<aggBlocks, 256>>>(py);
        k_gemm_mma<false><<<GEMM_NB, 256>>>(papk, pwpk + l*DD*DD, bs + l*DD, py, nullptr, batch);
    }
    k_agg<<<aggBlocks, 256>>>(py);
    k_gemm_mma<true><<<GEMM_NB, 256>>>(papk, pwpk + 4*DD*DD, bs + 4*DD, nullptr, out, batch);
}

// round 15
// speedup vs baseline: 1.2164x; 1.0503x over previous
#include <cuda_runtime.h>
#include <cuda_fp16.h>
#include <cstdint>

#define NN   50000
#define EE   600000
#define FEAT 11
#define DD   128
#define BBATCH 500
#define MAXA 100
#define NLAYERS 5
#define DENSE (BBATCH*MAXA*DD)   /* 6,400,000 */
#define MASKN (BBATCH*MAXA)      /* 50,000 */

#define SCAN_BS   1024
#define SCAN_NB   ((NN + SCAN_BS - 1) / SCAN_BS)   /* 49 */
#define SCAN_FLAG (1 << 30)

#define TILE_M    128
#define GEMM_NB   ((NN + TILE_M - 1) / TILE_M)     /* 391 */
#define NNP       (GEMM_NB * TILE_M)               /* 50048, padded */

// merged-kernel block ranges
#define PWB  ((NLAYERS*DD*DD + 255)/256)           /* 320  prepw blocks  */
#define HB   ((EE + 255)/256)                      /* 2344 hist blocks   */
#define CSRB ((EE + 255)/256)                      /* 2344 csr blocks    */
#define EXPB ((NN + 31)/32)                        /* 1563 expand blocks (4 nodes/warp) */

// -------- scratch (static device globals; zero-initialized, no runtime alloc) --------
// INVARIANT across graph replays: g_deg == 0, g_counts == 0, g_bsum == 0 at entry.
__device__ __half g_y[NN*DD];                  // y = dinv * x, fp16 (12.8 MB)
__device__ __half g_apk[NNP*DD];               // aggregated A, fp16 (pad rows stay 0)
__device__ __half g_wpk[NLAYERS*DD*DD];        // Wt [l][n][k] fp16, fragment-paired word order
__device__ float g_dinv[NN];
__device__ int   g_deg[NN];
__device__ int   g_rowstart[NN+1];
__device__ int   g_cursor[NN];
__device__ int   g_csr_src[EE];
__device__ int   g_counts[BBATCH];
__device__ int   g_ptr[BBATCH];
__device__ int   g_bsum[SCAN_NB];

// ---------------- prep: W transpose + degree/count histogram (merged) ----------------
__global__ void k_prep_hist(const float* __restrict__ Ws,
                            const int* __restrict__ col, const int* __restrict__ batch)
{
    if (blockIdx.x < PWB) {
        int idx = blockIdx.x * 256 + threadIdx.x;
        if (idx >= NLAYERS*DD*DD) return;
        int l = idx >> 14;
        int r = idx & 16383;
        int n = r >> 7;
        int k = r & 127;
        float v = Ws[l*DD*DD + k*DD + n];
        int w = k >> 1;
        int p = ((w >> 3) << 2) | (w & 3);
        int c = (w >> 2) & 1;
        int dst = (l*DD + n) * DD + p*4 + c*2 + (k & 1);
        g_wpk[dst] = __float2half_rn(v);
        return;
    }
    int i = (blockIdx.x - PWB) * 256 + threadIdx.x;
    if (i < EE) atomicAdd(&g_deg[col[i]], 1);
    if (i < NN) atomicAdd(&g_counts[batch[i]], 1);
}

// -------- fused scan: local scan + flagged publish + predecessor poll + apply --------
__global__ __launch_bounds__(SCAN_BS)
void k_scan()
{
    __shared__ int warp_sums[32];
    __shared__ int s_boff;
    int tid  = threadIdx.x;
    int lane = tid & 31;
    int wid  = tid >> 5;
    int i    = blockIdx.x * SCAN_BS + tid;

    int v0 = (i < NN) ? g_deg[i] : 0;
    if (i < NN) {
        g_dinv[i] = rsqrtf((float)v0 + 2.0f);
        g_deg[i]  = 0;                       // restore invariant
    }
    int v  = v0;
    #pragma unroll
    for (int off = 1; off < 32; off <<= 1) {
        int t = __shfl_up_sync(0xffffffffu, v, off);
        if (lane >= off) v += t;
    }
    if (lane == 31) warp_sums[wid] = v;
    __syncthreads();
    if (wid == 0) {
        int s = warp_sums[lane];
        #pragma unroll
        for (int off = 1; off < 32; off <<= 1) {
            int t = __shfl_up_sync(0xffffffffu, s, off);
            if (lane >= off) s += t;
        }
        warp_sums[lane] = s;
    }
    __syncthreads();
    int incl = v + (wid ? warp_sums[wid-1] : 0);

    if (tid == 0) {
        int total = warp_sums[31];
        atomicExch(&g_bsum[blockIdx.x], total | SCAN_FLAG);
    }

    if (wid == 1) {
        int sum = 0;
        for (int p = lane; p < blockIdx.x; p += 32) {
            int bv;
            do { bv = atomicAdd(&g_bsum[p], 0); } while (!(bv & SCAN_FLAG));
            sum += bv & ~SCAN_FLAG;
        }
        #pragma unroll
        for (int off = 16; off > 0; off >>= 1)
            sum += __shfl_down_sync(0xffffffffu, sum, off);
        if (lane == 0) s_boff = sum;
    }
    __syncthreads();
    int boff = s_boff;

    if (i < NN) {
        g_rowstart[i+1] = incl + boff;
        g_cursor[i]     = incl - v0 + boff;
    }

    if (blockIdx.x == 0) {
        if (tid == 0) g_rowstart[0] = 0;
        int c = (tid < BBATCH) ? g_counts[tid] : 0;
        int vv = c;
        #pragma unroll
        for (int off = 1; off < 32; off <<= 1) {
            int t = __shfl_up_sync(0xffffffffu, vv, off);
            if (lane >= off) vv += t;
        }
        __syncthreads();
        if (lane == 31) warp_sums[wid] = vv;
        __syncthreads();
        if (wid == 0) {
            int s = warp_sums[lane];
            #pragma unroll
            for (int off = 1; off < 32; off <<= 1) {
                int t = __shfl_up_sync(0xffffffffu, s, off);
                if (lane >= off) s += t;
            }
            warp_sums[lane] = s;
        }
        __syncthreads();
        int incl2 = vv + (wid ? warp_sums[wid-1] : 0);
        if (tid < BBATCH) {
            g_ptr[tid]    = incl2 - c;
            g_counts[tid] = 0;
        }
    }
}

// ---- merged: csr build + mask write + log-expansion (4 nodes/warp) ----
__global__ __launch_bounds__(256)
void k_csr_expand(const int* __restrict__ conn, const int* __restrict__ batch,
                  float* __restrict__ out, int out_size,
                  const float* __restrict__ atoms,
                  const float* __restrict__ Wexp,
                  const float* __restrict__ bexp)
{
    __shared__ float sW[FEAT*DD];
    __shared__ float sb[DD];

    if (blockIdx.x < CSRB) {
        int e = blockIdx.x * 256 + threadIdx.x;
        if (blockIdx.x == 0 && threadIdx.x < SCAN_NB)
            g_bsum[threadIdx.x] = 0;
        if (e < NN && out_size >= DENSE + MASKN) {
            int b = batch[e];
            out[DENSE + b*MAXA + (e - g_ptr[b])] = 1.0f;
        }
        if (e >= EE) return;
        int r = conn[e];
        int c = conn[EE + e];
        int slot = atomicAdd(&g_cursor[c], 1);
        g_csr_src[slot] = r;
        return;
    }

    int tid = threadIdx.x;
    for (int i = tid; i < FEAT*DD; i += 256) sW[i] = Wexp[i];
    if (tid < DD) sb[tid] = bexp[tid];
    __syncthreads();

    int nb   = blockIdx.x - CSRB;
    int wid  = tid >> 5;
    int lane = tid & 31;
    int d0   = lane * 4;

    #pragma unroll
    for (int it = 0; it < 4; it++) {
        int n = nb * 32 + wid * 4 + it;
        if (n >= NN) break;

        float la = 0.f;
        if (lane < FEAT) la = logf(atoms[n*FEAT + lane] + 1.0f);

        float acc[4];
        #pragma unroll
        for (int q = 0; q < 4; q++) acc[q] = sb[d0 + q];
        #pragma unroll
        for (int f = 0; f < FEAT; f++) {
            float lf = __shfl_sync(0xffffffffu, la, f);
            #pragma unroll
            for (int q = 0; q < 4; q++)
                acc[q] = fmaf(lf, sW[f*DD + d0 + q], acc[q]);
        }
        float di = g_dinv[n];
        __half2 h0 = __floats2half2_rn(acc[0]*di, acc[1]*di);
        __half2 h1 = __floats2half2_rn(acc[2]*di, acc[3]*di);
        uint2 p;
        p.x = *reinterpret_cast<uint32_t*>(&h0);
        p.y = *reinterpret_cast<uint32_t*>(&h1);
        reinterpret_cast<uint2*>(g_y)[n*32 + lane] = p;
    }
}

// ------- aggregation: agg[w] = dinv[w]*(sum_src y[src] + 2*y[w]) -------
// MLP=8 batched gathers; edge PAIRS pre-summed in fp16 (one HADD2 rounding per
// pair, ~8e-5 added rel err), then fp32 accumulation.
__global__ void k_agg(const __half* __restrict__ y)
{
    int w = (blockIdx.x * blockDim.x + threadIdx.x) >> 5;
    if (w >= NN) return;
    int lane = threadIdx.x & 31;
    const uint2* yr = reinterpret_cast<const uint2*>(y);

    uint2 sv = yr[w*32 + lane];
    float2 s0 = __half22float2(*reinterpret_cast<__half2*>(&sv.x));
    float2 s1 = __half22float2(*reinterpret_cast<__half2*>(&sv.y));
    float4 acc = make_float4(2.f*s0.x, 2.f*s0.y, 2.f*s1.x, 2.f*s1.y);

    int s = g_rowstart[w];
    int e = g_rowstart[w+1];
    int j = s;

    for (; j + 8 <= e; j += 8) {
        int idx[8];
        #pragma unroll
        for (int q = 0; q < 8; q++) idx[q] = g_csr_src[j + q];
        uint2 u[8];
        #pragma unroll
        for (int q = 0; q < 8; q++) u[q] = yr[idx[q]*32 + lane];
        #pragma unroll
        for (int q = 0; q < 4; q++) {
            __half2 px = __hadd2(*reinterpret_cast<__half2*>(&u[2*q].x),
                                 *reinterpret_cast<__half2*>(&u[2*q+1].x));
            __half2 py = __hadd2(*reinterpret_cast<__half2*>(&u[2*q].y),
                                 *reinterpret_cast<__half2*>(&u[2*q+1].y));
            float2 fx = __half22float2(px);
            float2 fy = __half22float2(py);
            acc.x += fx.x; acc.y += fx.y; acc.z += fy.x; acc.w += fy.y;
        }
    }
    for (; j + 2 <= e; j += 2) {
        int   i0 = g_csr_src[j], i1 = g_csr_src[j+1];
        uint2 u0 = yr[i0*32 + lane];
        uint2 u1 = yr[i1*32 + lane];
        __half2 px = __hadd2(*reinterpret_cast<__half2*>(&u0.x),
                             *reinterpret_cast<__half2*>(&u1.x));
        __half2 py = __hadd2(*reinterpret_cast<__half2*>(&u0.y),
                             *reinterpret_cast<__half2*>(&u1.y));
        float2 fx = __half22float2(px);
        float2 fy = __half22float2(py);
        acc.x += fx.x; acc.y += fx.y; acc.z += fy.x; acc.w += fy.y;
    }
    if (j < e) {
        int   src = g_csr_src[j];
        uint2 u   = yr[src*32 + lane];
        float2 a  = __half22float2(*reinterpret_cast<__half2*>(&u.x));
        float2 b  = __half22float2(*reinterpret_cast<__half2*>(&u.y));
        acc.x += a.x; acc.y += a.y; acc.z += b.x; acc.w += b.y;
    }

    float di = g_dinv[w];
    __half2 h0 = __floats2half2_rn(acc.x*di, acc.y*di);
    __half2 h1 = __floats2half2_rn(acc.z*di, acc.w*di);
    uint2 p;
    p.x = *reinterpret_cast<uint32_t*>(&h0);
    p.y = *reinterpret_cast<uint32_t*>(&h1);
    reinterpret_cast<uint2*>(g_apk)[w*32 + lane] = p;
}

// ---------------- fp16 mma.sync GEMM (single term): relu(A W^T + b) ----------------
__device__ __forceinline__ void mma_f16(float* d, const uint32_t* a, const uint32_t* b)
{
    asm volatile(
        "mma.sync.aligned.m16n8k16.row.col.f32.f16.f16.f32 "
        "{%0,%1,%2,%3}, {%4,%5,%6,%7}, {%8,%9}, {%0,%1,%2,%3};"
        : "+f"(d[0]), "+f"(d[1]), "+f"(d[2]), "+f"(d[3])
        : "r"(a[0]), "r"(a[1]), "r"(a[2]), "r"(a[3]), "r"(b[0]), "r"(b[1]));
}

// non-LAST: writes y = dinv*relu(..) as fp16. LAST: scatters fp32 into dense out.
template<bool LAST>
__global__ __launch_bounds__(256)
void k_gemm_mma(const __half* __restrict__ apk,
                const __half* __restrict__ wpk,
                const float* __restrict__ bias,
                __half* __restrict__ yout,
                float* __restrict__ dout,
                const int* __restrict__ batch)
{
    int tid    = threadIdx.x;
    int lane   = tid & 31;
    int wid    = tid >> 5;
    int warp_m = wid & 3;
    int warp_n = wid >> 2;
    int g      = lane >> 2;
    int tq     = lane & 3;

    int rowBase = blockIdx.x * TILE_M + warp_m * 32;
    int colBase = warp_n * 64;

    const uint32_t* AP = reinterpret_cast<const uint32_t*>(apk);
    const uint2*    BP = reinterpret_cast<const uint2*>(wpk);

    const uint32_t* a0 = AP + (rowBase + g     ) * 64;
    const uint32_t* a1 = AP + (rowBase + g +  8) * 64;
    const uint32_t* a2 = AP + (rowBase + g + 16) * 64;
    const uint32_t* a3 = AP + (rowBase + g + 24) * 64;
    const uint2*    bp = BP + (colBase + g) * 32;

    float d[2][8][4];
    #pragma unroll
    for (int mt = 0; mt < 2; mt++)
        #pragma unroll
        for (int nt = 0; nt < 8; nt++)
            #pragma unroll
            for (int q = 0; q < 4; q++) d[mt][nt][q] = 0.0f;

    #pragma unroll 4
    for (int ks = 0; ks < 8; ks++) {
        int o0 = ks*8 + tq;
        int o1 = o0 + 4;

        uint32_t aF[2][4];
        aF[0][0] = a0[o0]; aF[0][1] = a1[o0]; aF[0][2] = a0[o1]; aF[0][3] = a1[o1];
        aF[1][0] = a2[o0]; aF[1][1] = a3[o0]; aF[1][2] = a2[o1]; aF[1][3] = a3[o1];

        uint32_t bF[8][2];
        #pragma unroll
        for (int nt = 0; nt < 8; nt++) {
            uint2 wv = bp[nt*256 + ks*4 + tq];
            bF[nt][0] = wv.x; bF[nt][1] = wv.y;
        }
        #pragma unroll
        for (int mt = 0; mt < 2; mt++)
            #pragma unroll
            for (int nt = 0; nt < 8; nt++)
                mma_f16(d[mt][nt], aF[mt], bF[nt]);
    }

    #pragma unroll
    for (int mt = 0; mt < 2; mt++) {
        int m0 = rowBase + mt*16 + g;
        int m1 = m0 + 8;
        if (LAST) {
            int or0 = 0, or1 = 0;
            if (m0 < NN) { int b = batch[m0]; or0 = b*MAXA + (m0 - g_ptr[b]); }
            if (m1 < NN) { int b = batch[m1]; or1 = b*MAXA + (m1 - g_ptr[b]); }
            #pragma unroll
            for (int nt = 0; nt < 8; nt++) {
                int cn = colBase + nt*8 + tq*2;
                float2 bv = *reinterpret_cast<const float2*>(bias + cn);
                if (m0 < NN) {
                    float2 o;
                    o.x = fmaxf(d[mt][nt][0] + bv.x, 0.f);
                    o.y = fmaxf(d[mt][nt][1] + bv.y, 0.f);
                    *reinterpret_cast<float2*>(dout + or0*DD + cn) = o;
                }
                if (m1 < NN) {
                    float2 o;
                    o.x = fmaxf(d[mt][nt][2] + bv.x, 0.f);
                    o.y = fmaxf(d[mt][nt][3] + bv.y, 0.f);
                    *reinterpret_cast<float2*>(dout + or1*DD + cn) = o;
                }
            }
        } else {
            float di0 = (m0 < NN) ? g_dinv[m0] : 0.f;
            float di1 = (m1 < NN) ? g_dinv[m1] : 0.f;
            #pragma unroll
            for (int nt = 0; nt < 8; nt++) {
                int cn = colBase + nt*8 + tq*2;
                float2 bv = *reinterpret_cast<const float2*>(bias + cn);
                if (m0 < NN) {
                    float ox = fmaxf(d[mt][nt][0] + bv.x, 0.f) * di0;
                    float oy = fmaxf(d[mt][nt][1] + bv.y, 0.f) * di0;
                    *reinterpret_cast<__half2*>(yout + m0*DD + cn) = __floats2half2_rn(ox, oy);
                }
                if (m1 < NN) {
                    float ox = fmaxf(d[mt][nt][2] + bv.x, 0.f) * di1;
                    float oy = fmaxf(d[mt][nt][3] + bv.y, 0.f) * di1;
                    *reinterpret_cast<__half2*>(yout + m1*DD + cn) = __floats2half2_rn(ox, oy);
                }
            }
        }
    }
}

// ---------------- tail zero (only for any region beyond dense+mask) ----------------
__global__ void k_zero_tail(float* __restrict__ out, int start, int n)
{
    int i = blockIdx.x * blockDim.x + threadIdx.x;
    if (i < n) out[start + i] = 0.0f;
}

// ---------------- launch ----------------
extern "C" void kernel_launch(void* const* d_in, const int* in_sizes, int n_in,
                              void* d_out, int out_size)
{
    const float* atoms = (const float*)d_in[0];
    const int*   conn  = (const int*)d_in[1];
    const int*   batch = (const int*)d_in[2];
    const float* W_exp = (const float*)d_in[3];
    const float* b_exp = (const float*)d_in[4];
    const float* Ws    = (const float*)d_in[5];
    const float* bs    = (const float*)d_in[6];
    float* out = (float*)d_out;

    __half *py, *papk, *pwpk;
    cudaGetSymbolAddress((void**)&py,   g_y);
    cudaGetSymbolAddress((void**)&papk, g_apk);
    cudaGetSymbolAddress((void**)&pwpk, g_wpk);

    k_prep_hist<<<PWB + HB, 256>>>(Ws, conn + EE, batch);
    k_scan<<<SCAN_NB, SCAN_BS>>>();
    k_csr_expand<<<CSRB + EXPB, 256>>>(conn, batch, out, out_size, atoms, W_exp, b_exp);

    int tail = out_size - (DENSE + MASKN);
    if (tail > 0)
        k_zero_tail<<<(tail + 255)/256, 256>>>(out, DENSE + MASKN, tail);

    int aggBlocks = (NN*32 + 255)/256;
    for (int l = 0; l < NLAYERS - 1; l++) {
        k_agg<<<aggBlocks, 256>>>(py);
        k_gemm_mma<false><<<GEMM_NB, 256>>>(papk, pwpk + l*DD*DD, bs + l*DD, py, nullptr, batch);
    }
    k_agg<<<aggBlocks, 256>>>(py);
    k_gemm_mma<true><<<GEMM_NB, 256>>>(papk, pwpk + 4*DD*DD, bs + 4*DD, nullptr, out, batch);
}